// round 5
// baseline (speedup 1.0000x reference)
#include <cuda_runtime.h>
#include <math.h>
#include <float.h>
#include <stdint.h>

#define MAXN 4096
#define MAXE 65536
#define MAXD 128   // max distinct neighbors per destination (Poisson(16) tail ~0 beyond 100)

// ------------------------- device scratch (module-allocated, no cudaMalloc) -------------------------
__device__ float dA0[(size_t)MAXN * MAXN];       // 67 MB
__device__ float dB0[(size_t)MAXN * MAXN];       // 67 MB  (augment(A0))
__device__ float dA1[2048 * 2048];
__device__ float dB1[2048 * 2048];
__device__ float dMS[2048 * 2048];               // M = A + I scratch for dense augment
__device__ float dA2[1024 * 1024];
__device__ float dB2[1024 * 1024];
__device__ float dA3[512 * 512];

__device__ float dY[(size_t)MAXN * 128];
__device__ float dZ[(size_t)MAXN * 128];
__device__ float dACC[(size_t)MAXN * 128];
__device__ float dZH[(size_t)MAXN * 128];        // tf32 split hi
__device__ float dZL[(size_t)MAXN * 128];        // tf32 split lo

__device__ float dX0[(size_t)MAXN * 64];
__device__ float dX1[2048 * 64];
__device__ float dX2[1024 * 64];
__device__ float dX3[512 * 64];
__device__ float dHP[(size_t)MAXN * 64];         // pooled-x / up intermediate
__device__ float dHA[(size_t)MAXN * 64];         // up-path ping
__device__ float dHB[(size_t)MAXN * 64];         // up-path pong
__device__ float dHOUT[(size_t)MAXN * 128];
__device__ float dU[(size_t)MAXN * 128];
__device__ float dRESID[(size_t)MAXN * 128];
__device__ float dHF[(size_t)MAXN * 512];        // GAT1 transformed features
__device__ float dG1[(size_t)MAXN * 512];        // GAT1 output

__device__ float dES[(size_t)MAXN * 4];
__device__ float dED[(size_t)MAXN * 4];
__device__ float dScore[MAXN];
__device__ int   dPerm1[2048];
__device__ int   dPerm2[1024];
__device__ int   dPerm3[512];
__device__ float dVals1[2048];
__device__ float dVals2[1024];
__device__ float dVals3[512];
__device__ float dDinv[MAXN];
__device__ float dCorr[MAXN];

__device__ int dCntS[MAXN], dCntD[MAXN];
__device__ int dOffS[MAXN + 1], dOffD[MAXN + 1];
__device__ int dFillS[MAXN], dFillD[MAXN];
__device__ int dLstS[MAXE], dLstD[MAXE];
__device__ int dNbrCnt[MAXN];
__device__ int dNbrLst[(size_t)MAXN * MAXD];

// ------------------------- small helpers -------------------------
__device__ __forceinline__ float lrelu(float x) { return x > 0.f ? x : 0.2f * x; }

__global__ void k_zero_f(float* p, size_t n) {
    size_t i = (size_t)blockIdx.x * blockDim.x + threadIdx.x;
    size_t stride = (size_t)gridDim.x * blockDim.x;
    for (; i < n; i += stride) p[i] = 0.f;
}
__global__ void k_zero_i(int* p, int n) {
    int i = blockIdx.x * blockDim.x + threadIdx.x;
    if (i < n) p[i] = 0;
}

// build A0 (dense) and per-node degree counts
__global__ void k_build_a0(const int* ei, int E, int n, float* A, int* cntS, int* cntD) {
    int e = blockIdx.x * blockDim.x + threadIdx.x;
    if (e >= E) return;
    int s = ei[e], d = ei[E + e];
    atomicAdd(&A[(size_t)d * n + s], 1.f);
    atomicAdd(&cntS[s], 1);
    atomicAdd(&cntD[d], 1);
}

// single-block scan: off[0]=0, off[i+1]=sum cnt[0..i]
__global__ void k_scan(const int* cnt, int* off, int n) {
    __shared__ int ps[1024];
    int t = threadIdx.x;
    int chunk = (n + 1023) >> 10;
    int base = t * chunk;
    int s = 0;
    for (int j = 0; j < chunk; j++) { int idx = base + j; if (idx < n) s += cnt[idx]; }
    ps[t] = s; __syncthreads();
    for (int d = 1; d < 1024; d <<= 1) {
        int v = (t >= d) ? ps[t - d] : 0;
        __syncthreads();
        ps[t] += v;
        __syncthreads();
    }
    int run = (t > 0) ? ps[t - 1] : 0;
    if (t == 0) off[0] = 0;
    for (int j = 0; j < chunk; j++) {
        int idx = base + j;
        if (idx < n) { run += cnt[idx]; off[idx + 1] = run; }
    }
}

__global__ void k_csr_fill(const int* ei, int E, const int* offS, const int* offD,
                           int* fillS, int* fillD, int* lstS, int* lstD) {
    int e = blockIdx.x * blockDim.x + threadIdx.x;
    if (e >= E) return;
    int s = ei[e], d = ei[E + e];
    int pS = atomicAdd(&fillS[s], 1);
    lstS[offS[s] + pS] = d;
    int pD = atomicAdd(&fillD[d], 1);
    lstD[offD[d] + pD] = s;
}

// C += A0 @ A0 via 2-path pair enumeration: edge(j->k) x edge(k->i) => C[i,j]+=1
__global__ void k_spgemm_pairs(const int* cntS, const int* cntD, const int* offS, const int* offD,
                               const int* lstS, const int* lstD, float* C, int n) {
    int k = blockIdx.x;
    int ni = cntS[k], nj = cntD[k];
    long tot = (long)ni * nj;
    int oS = offS[k], oD = offD[k];
    for (long p = threadIdx.x; p < tot; p += blockDim.x) {
        int i = lstS[oS + (int)(p / nj)];
        int j = lstD[oD + (int)(p % nj)];
        atomicAdd(&C[(size_t)i * n + j], 1.f);
    }
}

__global__ void k_add_2a(const int* ei, int E, int n, float* C) {
    int e = blockIdx.x * blockDim.x + threadIdx.x;
    if (e >= E) return;
    int s = ei[e], d = ei[E + e];
    atomicAdd(&C[(size_t)d * n + s], 2.f);
}

__global__ void k_zero_diag(float* C, int n) {
    int i = blockIdx.x * blockDim.x + threadIdx.x;
    if (i < n) C[(size_t)i * n + i] = 0.f;
}

__global__ void k_copy_addI(const float* A, float* M, int n) {
    size_t idx = (size_t)blockIdx.x * blockDim.x + threadIdx.x;
    size_t tot = (size_t)n * n;
    size_t stride = (size_t)gridDim.x * blockDim.x;
    for (; idx < tot; idx += stride) {
        int i = (int)(idx / n), j = (int)(idx % n);
        M[idx] = A[idx] + (i == j ? 1.f : 0.f);
    }
}

// ------------------------- SGEMM: C[M,N] = A[M,K] @ B[K,N] (+bias per col) -------------------------
__global__ void k_gemm(const float* __restrict__ A, const float* __restrict__ B,
                       float* __restrict__ C, int M, int N, int K,
                       const float* __restrict__ bias) {
    __shared__ float As[16][64];
    __shared__ float Bs[16][64];
    int tid = threadIdx.x;
    int tx = tid & 15, ty = tid >> 4;
    int bm = blockIdx.y * 64, bn = blockIdx.x * 64;
    float acc[4][4] = {};
    for (int k0 = 0; k0 < K; k0 += 16) {
#pragma unroll
        for (int l = 0; l < 4; l++) {
            int e = tid + l * 256;
            int mm = e >> 4, kk = e & 15;
            int gr = bm + mm, gc = k0 + kk;
            As[kk][mm] = (gr < M && gc < K) ? A[(size_t)gr * K + gc] : 0.f;
        }
#pragma unroll
        for (int l = 0; l < 4; l++) {
            int e = tid + l * 256;
            int kk = e >> 6, nn = e & 63;
            int gr = k0 + kk, gc = bn + nn;
            Bs[kk][nn] = (gr < K && gc < N) ? B[(size_t)gr * N + gc] : 0.f;
        }
        __syncthreads();
#pragma unroll
        for (int kk = 0; kk < 16; kk++) {
            float a[4], b[4];
#pragma unroll
            for (int i = 0; i < 4; i++) a[i] = As[kk][ty * 4 + i];
#pragma unroll
            for (int j = 0; j < 4; j++) b[j] = Bs[kk][tx * 4 + j];
#pragma unroll
            for (int i = 0; i < 4; i++)
#pragma unroll
                for (int j = 0; j < 4; j++) acc[i][j] += a[i] * b[j];
        }
        __syncthreads();
    }
#pragma unroll
    for (int i = 0; i < 4; i++) {
        int r = bm + ty * 4 + i;
        if (r >= M) continue;
#pragma unroll
        for (int j = 0; j < 4; j++) {
            int c = bn + tx * 4 + j;
            if (c >= N) continue;
            float v = acc[i][j];
            if (bias) v += bias[c];
            C[(size_t)r * N + c] = v;
        }
    }
}

// ------------------------- TF32 tensor-core GEMM -------------------------
// C[M,N] = A[M,K] @ B[K,N] (beta=0) or += (beta=1). fp32 I/O interpreted as tf32
// operands (callers guarantee tf32-exact inputs: small integers or rna-split halves).
__device__ __forceinline__ void mma_tf32_op(float* c, const uint32_t* a, const uint32_t* b) {
    asm volatile(
        "mma.sync.aligned.m16n8k8.row.col.f32.tf32.tf32.f32 "
        "{%0,%1,%2,%3}, {%4,%5,%6,%7}, {%8,%9}, {%0,%1,%2,%3};"
        : "+f"(c[0]), "+f"(c[1]), "+f"(c[2]), "+f"(c[3])
        : "r"(a[0]), "r"(a[1]), "r"(a[2]), "r"(a[3]), "r"(b[0]), "r"(b[1]));
}

__global__ void __launch_bounds__(256)
k_mma_tf32(const float* __restrict__ A, const float* __restrict__ B,
           float* __restrict__ C, int M, int N, int K, int beta) {
    __shared__ float As[128][36];   // [m][k], stride-36 pad: conflict-free frag loads
    __shared__ float Bs[128][36];   // [n][k]
    int tid = threadIdx.x;
    int lane = tid & 31, warp = tid >> 5;
    int wm = warp >> 2, wn = warp & 3;             // 2 x 4 warp grid (64x32 per warp)
    int g = lane >> 2, tg = lane & 3;
    int bm = blockIdx.y * 128, bn = blockIdx.x * 128;
    float acc[4][4][4] = {};

    for (int k0 = 0; k0 < K; k0 += 32) {
        // A tile: 128 rows x 32 cols, float4 coalesced along K
#pragma unroll
        for (int i = 0; i < 4; i++) {
            int flat = tid + i * 256;
            int r = flat >> 3, c4 = (flat & 7) * 4;
            float4 v = make_float4(0.f, 0.f, 0.f, 0.f);
            if (bm + r < M) v = *(const float4*)&A[(size_t)(bm + r) * K + k0 + c4];
            *(float4*)&As[r][c4] = v;
        }
        // B tile: 32 rows (k) x 128 cols (n), transpose into [n][k]
#pragma unroll
        for (int i = 0; i < 4; i++) {
            int flat = tid + i * 256;
            int kr = flat >> 5, c4 = (flat & 31) * 4;
            float v0 = 0.f, v1 = 0.f, v2 = 0.f, v3 = 0.f;
            if (bn + c4 + 3 < N) {
                float4 v = *(const float4*)&B[(size_t)(k0 + kr) * N + bn + c4];
                v0 = v.x; v1 = v.y; v2 = v.z; v3 = v.w;
            } else {
                const float* bp = &B[(size_t)(k0 + kr) * N];
                if (bn + c4 + 0 < N) v0 = bp[bn + c4 + 0];
                if (bn + c4 + 1 < N) v1 = bp[bn + c4 + 1];
                if (bn + c4 + 2 < N) v2 = bp[bn + c4 + 2];
                if (bn + c4 + 3 < N) v3 = bp[bn + c4 + 3];
            }
            Bs[c4 + 0][kr] = v0; Bs[c4 + 1][kr] = v1;
            Bs[c4 + 2][kr] = v2; Bs[c4 + 3][kr] = v3;
        }
        __syncthreads();
#pragma unroll
        for (int ks = 0; ks < 32; ks += 8) {
            uint32_t af[4][4], bf[4][2];
#pragma unroll
            for (int mt = 0; mt < 4; mt++) {
                int m = wm * 64 + mt * 16;
                af[mt][0] = __float_as_uint(As[m + g][ks + tg]);
                af[mt][1] = __float_as_uint(As[m + g + 8][ks + tg]);
                af[mt][2] = __float_as_uint(As[m + g][ks + tg + 4]);
                af[mt][3] = __float_as_uint(As[m + g + 8][ks + tg + 4]);
            }
#pragma unroll
            for (int nt = 0; nt < 4; nt++) {
                int n = wn * 32 + nt * 8;
                bf[nt][0] = __float_as_uint(Bs[n + g][ks + tg]);
                bf[nt][1] = __float_as_uint(Bs[n + g][ks + tg + 4]);
            }
#pragma unroll
            for (int mt = 0; mt < 4; mt++)
#pragma unroll
                for (int nt = 0; nt < 4; nt++)
                    mma_tf32_op(acc[mt][nt], af[mt], bf[nt]);
        }
        __syncthreads();
    }
    // epilogue
#pragma unroll
    for (int mt = 0; mt < 4; mt++) {
#pragma unroll
        for (int nt = 0; nt < 4; nt++) {
            int row0 = bm + wm * 64 + mt * 16 + g;
            int col = bn + wn * 32 + nt * 8 + tg * 2;
            float* c = acc[mt][nt];
            if (row0 < M) {
                float* p = &C[(size_t)row0 * N];
                if (col < N)     { p[col]     = beta ? p[col]     + c[0] : c[0]; }
                if (col + 1 < N) { p[col + 1] = beta ? p[col + 1] + c[1] : c[1]; }
            }
            int row1 = row0 + 8;
            if (row1 < M) {
                float* p = &C[(size_t)row1 * N];
                if (col < N)     { p[col]     = beta ? p[col]     + c[2] : c[2]; }
                if (col + 1 < N) { p[col + 1] = beta ? p[col + 1] + c[3] : c[3]; }
            }
        }
    }
}

// split z into tf32-exact hi + tf32-exact lo (Markidis split); hi+lo ~ z to ~2^-22 rel
__global__ void k_split(const float* __restrict__ z, float* __restrict__ hi,
                        float* __restrict__ lo, size_t n) {
    size_t idx = (size_t)blockIdx.x * blockDim.x + threadIdx.x;
    if (idx >= n) return;
    float v = z[idx];
    uint32_t hb; asm("cvt.rna.tf32.f32 %0, %1;" : "=r"(hb) : "f"(v));
    float h = __uint_as_float(hb);
    float l = v - h;
    uint32_t lb; asm("cvt.rna.tf32.f32 %0, %1;" : "=r"(lb) : "f"(l));
    hi[idx] = h;
    lo[idx] = __uint_as_float(lb);
}

// ------------------------- GCN pieces -------------------------
__global__ void k_rowstats(const float* A, int n, float* dinv, float* corr) {
    int r = blockIdx.x, t = threadIdx.x;
    __shared__ float sh[256];
    float s = 0.f;
    for (int j = t; j < n; j += 256) s += A[(size_t)r * n + j];
    sh[t] = s; __syncthreads();
    for (int st = 128; st > 0; st >>= 1) { if (t < st) sh[t] += sh[t + st]; __syncthreads(); }
    if (t == 0) {
        float diag = A[(size_t)r * n + r];
        float ex = (diag == 0.f) ? 2.f : 0.f;
        dinv[r] = 1.f / sqrtf(sh[0] + ex);
        corr[r] = ex;
    }
}

__global__ void k_scale_rows(const float* Y, const float* dinv, float* Z, int n, int F) {
    size_t idx = (size_t)blockIdx.x * blockDim.x + threadIdx.x;
    if (idx >= (size_t)n * F) return;
    Z[idx] = dinv[idx / F] * Y[idx];
}

__global__ void k_gcn_epi(const float* ACC, const float* Z, const float* dinv, const float* corr,
                          const float* b, float* out, int n, int F, int relu) {
    size_t idx = (size_t)blockIdx.x * blockDim.x + threadIdx.x;
    if (idx >= (size_t)n * F) return;
    int i = (int)(idx / F), f = (int)(idx % F);
    float v = dinv[i] * (ACC[idx] + corr[i] * Z[idx]) + b[f];
    if (relu) v = fmaxf(v, 0.f);
    out[idx] = v;
}

// ------------------------- pooling -------------------------
__global__ void k_score(const float* x, const float* p, float* score) { // F = 64, block 64
    int i = blockIdx.x, t = threadIdx.x;
    __shared__ float s1[64], s2[64];
    float xv = x[(size_t)i * 64 + t], pv = p[t];
    s1[t] = xv * pv; s2[t] = pv * pv; __syncthreads();
    for (int st = 32; st > 0; st >>= 1) {
        if (t < st) { s1[t] += s1[t + st]; s2[t] += s2[t + st]; }
        __syncthreads();
    }
    if (t == 0) score[i] = tanhf(s1[0] / sqrtf(s2[0]));
}

__global__ void k_topsort(const float* score, int n, int k, int N2, int* perm, float* vals) {
    __shared__ float sv[4096];
    __shared__ int si[4096];
    int t = threadIdx.x;
    for (int i = t; i < N2; i += blockDim.x) {
        if (i < n) { sv[i] = score[i]; si[i] = i; }
        else       { sv[i] = -FLT_MAX; si[i] = 0x3fffffff; }
    }
    __syncthreads();
    for (int size = 2; size <= N2; size <<= 1) {
        for (int stride = size >> 1; stride > 0; stride >>= 1) {
            for (int i = t; i < N2; i += blockDim.x) {
                int j = i ^ stride;
                if (j > i) {
                    float av = sv[i]; int ai = si[i];
                    float bv = sv[j]; int bi = si[j];
                    bool before = (av > bv) || (av == bv && ai < bi); // descending, stable
                    bool desc = ((i & size) == 0);
                    if (desc != before) { sv[i] = bv; si[i] = bi; sv[j] = av; si[j] = ai; }
                }
            }
            __syncthreads();
        }
    }
    for (int i = t; i < k; i += blockDim.x) { perm[i] = si[i]; vals[i] = sv[i]; }
}

__global__ void k_gatherA(const float* B, int ldB, const int* perm, float* Aout, int k) {
    int j = blockIdx.x * blockDim.x + threadIdx.x;
    int i = blockIdx.y;
    if (i < k && j < k) Aout[(size_t)i * k + j] = B[(size_t)perm[i] * ldB + perm[j]];
}

__global__ void k_gatherX(const float* X, int F, const int* perm, const float* vals, float* out, int k) {
    size_t idx = (size_t)blockIdx.x * blockDim.x + threadIdx.x;
    if (idx >= (size_t)k * F) return;
    int i = (int)(idx / F), f = (int)(idx % F);
    out[idx] = X[(size_t)perm[i] * F + f] * vals[i];
}

__global__ void k_copy(float* dst, const float* src, size_t n) {
    size_t i = (size_t)blockIdx.x * blockDim.x + threadIdx.x;
    size_t stride = (size_t)gridDim.x * blockDim.x;
    for (; i < n; i += stride) dst[i] = src[i];
}

__global__ void k_scatadd(float* h, const int* perm, const float* xl, int k, int F) {
    size_t idx = (size_t)blockIdx.x * blockDim.x + threadIdx.x;
    if (idx >= (size_t)k * F) return;
    int t = (int)(idx / F), f = (int)(idx % F);
    h[(size_t)perm[t] * F + f] += xl[idx];
}

// ------------------------- layernorm -------------------------
__global__ void k_ln(const float* h, const float* g, const float* b, float* u, int F) { // block = F = 128
    int row = blockIdx.x, t = threadIdx.x;
    __shared__ float sh[128];
    float v = h[(size_t)row * F + t];
    sh[t] = v; __syncthreads();
    for (int st = 64; st > 0; st >>= 1) { if (t < st) sh[t] += sh[t + st]; __syncthreads(); }
    float mu = sh[0] / F;
    __syncthreads();
    float dv = v - mu;
    sh[t] = dv * dv; __syncthreads();
    for (int st = 64; st > 0; st >>= 1) { if (t < st) sh[t] += sh[t + st]; __syncthreads(); }
    float var = sh[0] / F;
    u[(size_t)row * F + t] = dv * rsqrtf(var + 1e-6f) * g[t] + b[t];
}

// ------------------------- GAT -------------------------
__global__ void k_nbr(const float* A, int n, int* cnt, int* lst) { // block 128
    int d = blockIdx.x, t = threadIdx.x;
    int chunk = (n + 127) >> 7;
    int s0 = t * chunk;
    int c = 0;
    for (int j = 0; j < chunk; j++) {
        int s = s0 + j;
        if (s < n && (A[(size_t)d * n + s] > 0.f || s == d)) c++;
    }
    __shared__ int sc[128];
    sc[t] = c; __syncthreads();
    if (t == 0) {
        int run = 0;
        for (int i = 0; i < 128; i++) { int v = sc[i]; sc[i] = run; run += v; }
        cnt[d] = run > MAXD ? MAXD : run;
    }
    __syncthreads();
    int off = sc[t];
    for (int j = 0; j < chunk; j++) {
        int s = s0 + j;
        if (s < n && (A[(size_t)d * n + s] > 0.f || s == d)) {
            if (off < MAXD) lst[(size_t)d * MAXD + off] = s;
            off++;
        }
    }
}

__global__ void k_attcoef(const float* hf, int H, int C, const float* asrc, const float* adst,
                          float* es, float* ed) { // grid (n, H), block C=128
    int s = blockIdx.x, h = blockIdx.y, t = threadIdx.x;
    __shared__ float s1[128], s2[128];
    float x = hf[(size_t)s * H * C + h * C + t];
    s1[t] = x * asrc[h * C + t];
    s2[t] = x * adst[h * C + t];
    __syncthreads();
    for (int st = 64; st > 0; st >>= 1) {
        if (t < st) { s1[t] += s1[t + st]; s2[t] += s2[t + st]; }
        __syncthreads();
    }
    if (t == 0) { es[s * H + h] = s1[0]; ed[s * H + h] = s2[0]; }
}

__global__ void k_gatattn(const float* hf, const float* es, const float* ed,
                          const int* cnt, const int* lst, const float* bias,
                          const float* resid, float* out, int H, int C, int doElu) { // block 128
    int d = blockIdx.x, t = threadIdx.x;
    __shared__ int snb[MAXD];
    __shared__ float sw[MAXD];
    __shared__ float sred[128];
    int m = cnt[d];
    if (t < m) snb[t] = lst[(size_t)d * MAXD + t];
    __syncthreads();
    for (int h = 0; h < H; h++) {
        float edv = ed[d * H + h];
        float mx = -FLT_MAX;
        for (int i = t; i < m; i += 128) mx = fmaxf(mx, lrelu(edv + es[snb[i] * H + h]));
        sred[t] = mx; __syncthreads();
        for (int st = 64; st > 0; st >>= 1) { if (t < st) sred[t] = fmaxf(sred[t], sred[t + st]); __syncthreads(); }
        float M = sred[0];
        __syncthreads();
        float dp = 0.f;
        for (int i = t; i < m; i += 128) {
            float w = expf(lrelu(edv + es[snb[i] * H + h]) - M);
            sw[i] = w; dp += w;
        }
        sred[t] = dp; __syncthreads();
        for (int st = 64; st > 0; st >>= 1) { if (t < st) sred[t] += sred[t + st]; __syncthreads(); }
        float den = sred[0];
        __syncthreads();
        float num = 0.f;
        for (int i = 0; i < m; i++) num += sw[i] * hf[(size_t)snb[i] * H * C + h * C + t];
        float o = num / den + bias[h * C + t];
        if (doElu) o = o > 0.f ? o : (expf(o) - 1.f);
        if (resid) o += resid[(size_t)d * C + t];
        out[(size_t)d * H * C + h * C + t] = o;
        __syncthreads();
    }
}

// ------------------------- host orchestration -------------------------
static void h_gemm(float* C, const float* A, const float* B, int M, int N, int K, const float* bias) {
    dim3 g((N + 63) / 64, (M + 63) / 64);
    k_gemm<<<g, 256>>>(A, B, C, M, N, K, bias);
}

static void h_mma(float* C, const float* A, const float* B, int M, int N, int K, int beta) {
    dim3 g((N + 127) / 128, (M + 127) / 128);
    k_mma_tf32<<<g, 256>>>(A, B, C, M, N, K, beta);
}

// tf32=1: A holds tf32-exact small integers -> propagate via split-tf32 tensor cores.
static void h_gcn(const float* A, int n, const float* x, int Fin, const float* W, int Fout,
                  const float* bias, float* out, int relu, int tf32,
                  float* Y, float* Z, float* ACC, float* ZH, float* ZL,
                  float* dinv, float* corr) {
    h_gemm(Y, x, W, n, Fout, Fin, nullptr);                     // Y = x @ W
    k_rowstats<<<n, 256>>>(A, n, dinv, corr);
    int tot = n * Fout;
    k_scale_rows<<<(tot + 255) / 256, 256>>>(Y, dinv, Z, n, Fout);
    if (tf32) {
        k_split<<<(tot + 255) / 256, 256>>>(Z, ZH, ZL, (size_t)tot);
        h_mma(ACC, A, ZH, n, Fout, n, 0);                       // ACC  = A @ Zhi
        h_mma(ACC, A, ZL, n, Fout, n, 1);                       // ACC += A @ Zlo
    } else {
        h_gemm(ACC, A, Z, n, Fout, n, nullptr);                 // ACC = A @ Z
    }
    k_gcn_epi<<<(tot + 255) / 256, 256>>>(ACC, Z, dinv, corr, bias, out, n, Fout, relu);
}

extern "C" void kernel_launch(void* const* d_in, const int* in_sizes, int n_in,
                              void* d_out, int out_size) {
    const float* x        = (const float*)d_in[0];
    const int*   ei       = (const int*)d_in[1];
    const float* w0 = (const float*)d_in[2];  const float* b0 = (const float*)d_in[3];
    const float* w1 = (const float*)d_in[4];  const float* b1 = (const float*)d_in[5];
    const float* w2 = (const float*)d_in[6];  const float* b2 = (const float*)d_in[7];
    const float* w3 = (const float*)d_in[8];  const float* b3 = (const float*)d_in[9];
    const float* p1 = (const float*)d_in[10]; const float* p2 = (const float*)d_in[11];
    const float* p3 = (const float*)d_in[12];
    const float* uw0 = (const float*)d_in[13]; const float* ub0 = (const float*)d_in[14];
    const float* uw1 = (const float*)d_in[15]; const float* ub1 = (const float*)d_in[16];
    const float* uw2 = (const float*)d_in[17]; const float* ub2 = (const float*)d_in[18];
    const float* ln_g = (const float*)d_in[19]; const float* ln_b = (const float*)d_in[20];
    const float* res_w = (const float*)d_in[21]; const float* res_b = (const float*)d_in[22];
    const float* g1w = (const float*)d_in[23];
    const float* g1as = (const float*)d_in[24]; const float* g1ad = (const float*)d_in[25];
    const float* g1b = (const float*)d_in[26];
    const float* g2w = (const float*)d_in[27];
    const float* g2as = (const float*)d_in[28]; const float* g2ad = (const float*)d_in[29];
    const float* g2b = (const float*)d_in[30];

    int Hdim  = in_sizes[3];                 // 64
    int INF   = in_sizes[2] / Hdim;          // 3
    int N     = in_sizes[0] / INF;           // 4096
    int E     = in_sizes[1] / 2;             // 65536
    int OUT   = in_sizes[18];                // 128
    int HEADS = in_sizes[26] / OUT;          // 4

    // fetch device-symbol addresses
    float *A0, *B0, *A1, *B1, *MS, *A2, *B2, *A3;
    float *Y, *Z, *ACC, *ZH, *ZL, *X0, *X1, *X2, *X3, *HP, *HA, *HB, *HOUTp, *U, *RESID, *HF, *G1;
    float *ES, *ED, *SCORE, *V1, *V2, *V3, *DINV, *CORR;
    int *P1i, *P2i, *P3i, *CNTS, *CNTD, *OFFS, *OFFD, *FILLS, *FILLD, *LSTS, *LSTD, *NBC, *NBL;
    cudaGetSymbolAddress((void**)&A0, dA0);   cudaGetSymbolAddress((void**)&B0, dB0);
    cudaGetSymbolAddress((void**)&A1, dA1);   cudaGetSymbolAddress((void**)&B1, dB1);
    cudaGetSymbolAddress((void**)&MS, dMS);   cudaGetSymbolAddress((void**)&A2, dA2);
    cudaGetSymbolAddress((void**)&B2, dB2);   cudaGetSymbolAddress((void**)&A3, dA3);
    cudaGetSymbolAddress((void**)&Y, dY);     cudaGetSymbolAddress((void**)&Z, dZ);
    cudaGetSymbolAddress((void**)&ACC, dACC);
    cudaGetSymbolAddress((void**)&ZH, dZH);   cudaGetSymbolAddress((void**)&ZL, dZL);
    cudaGetSymbolAddress((void**)&X0, dX0);
    cudaGetSymbolAddress((void**)&X1, dX1);   cudaGetSymbolAddress((void**)&X2, dX2);
    cudaGetSymbolAddress((void**)&X3, dX3);   cudaGetSymbolAddress((void**)&HP, dHP);
    cudaGetSymbolAddress((void**)&HA, dHA);   cudaGetSymbolAddress((void**)&HB, dHB);
    cudaGetSymbolAddress((void**)&HOUTp, dHOUT); cudaGetSymbolAddress((void**)&U, dU);
    cudaGetSymbolAddress((void**)&RESID, dRESID); cudaGetSymbolAddress((void**)&HF, dHF);
    cudaGetSymbolAddress((void**)&G1, dG1);
    cudaGetSymbolAddress((void**)&ES, dES);   cudaGetSymbolAddress((void**)&ED, dED);
    cudaGetSymbolAddress((void**)&SCORE, dScore);
    cudaGetSymbolAddress((void**)&P1i, dPerm1); cudaGetSymbolAddress((void**)&P2i, dPerm2);
    cudaGetSymbolAddress((void**)&P3i, dPerm3);
    cudaGetSymbolAddress((void**)&V1, dVals1); cudaGetSymbolAddress((void**)&V2, dVals2);
    cudaGetSymbolAddress((void**)&V3, dVals3);
    cudaGetSymbolAddress((void**)&DINV, dDinv); cudaGetSymbolAddress((void**)&CORR, dCorr);
    cudaGetSymbolAddress((void**)&CNTS, dCntS); cudaGetSymbolAddress((void**)&CNTD, dCntD);
    cudaGetSymbolAddress((void**)&OFFS, dOffS); cudaGetSymbolAddress((void**)&OFFD, dOffD);
    cudaGetSymbolAddress((void**)&FILLS, dFillS); cudaGetSymbolAddress((void**)&FILLD, dFillD);
    cudaGetSymbolAddress((void**)&LSTS, dLstS); cudaGetSymbolAddress((void**)&LSTD, dLstD);
    cudaGetSymbolAddress((void**)&NBC, dNbrCnt); cudaGetSymbolAddress((void**)&NBL, dNbrLst);

    int k1 = (N + 1) / 2, k2 = (k1 + 1) / 2, k3 = (k2 + 1) / 2;

    // ---- build A0 and augment(A0)=B0 via sparse 2-paths ----
    k_zero_f<<<4096, 256>>>(A0, (size_t)N * N);
    k_zero_f<<<4096, 256>>>(B0, (size_t)N * N);
    k_zero_i<<<(N + 255) / 256, 256>>>(CNTS, N);
    k_zero_i<<<(N + 255) / 256, 256>>>(CNTD, N);
    k_zero_i<<<(N + 255) / 256, 256>>>(FILLS, N);
    k_zero_i<<<(N + 255) / 256, 256>>>(FILLD, N);
    k_build_a0<<<(E + 255) / 256, 256>>>(ei, E, N, A0, CNTS, CNTD);
    k_scan<<<1, 1024>>>(CNTS, OFFS, N);
    k_scan<<<1, 1024>>>(CNTD, OFFD, N);
    k_csr_fill<<<(E + 255) / 256, 256>>>(ei, E, OFFS, OFFD, FILLS, FILLD, LSTS, LSTD);
    k_spgemm_pairs<<<N, 256>>>(CNTS, CNTD, OFFS, OFFD, LSTS, LSTD, B0, N);
    k_add_2a<<<(E + 255) / 256, 256>>>(ei, E, N, B0);
    k_zero_diag<<<(N + 255) / 256, 256>>>(B0, N);

    // ---- down path ----
    // A0 entries: small integers -> tf32-exact
    h_gcn(A0, N, x, INF, w0, Hdim, b0, X0, 1, 1, Y, Z, ACC, ZH, ZL, DINV, CORR);

    // pool1 (from B0)
    k_score<<<N, 64>>>(X0, p1, SCORE);
    { int N2 = 1; while (N2 < N) N2 <<= 1;
      k_topsort<<<1, 1024>>>(SCORE, N, k1, N2, P1i, V1); }
    { dim3 g((k1 + 255) / 256, k1); k_gatherA<<<g, 256>>>(B0, N, P1i, A1, k1); }
    k_gatherX<<<(k1 * Hdim + 255) / 256, 256>>>(X0, Hdim, P1i, V1, HP, k1);
    h_gcn(A1, k1, HP, Hdim, w1, Hdim, b1, X1, 1, 1, Y, Z, ACC, ZH, ZL, DINV, CORR);

    // augment(A1) -> B1 (dense, tf32 tensor cores; MS holds small integers -> exact)
    k_copy_addI<<<4096, 256>>>(A1, MS, k1);
    h_mma(B1, MS, MS, k1, k1, k1, 0);
    k_zero_diag<<<(k1 + 255) / 256, 256>>>(B1, k1);

    // pool2
    k_score<<<k1, 64>>>(X1, p2, SCORE);
    { int N2 = 1; while (N2 < k1) N2 <<= 1;
      k_topsort<<<1, 1024>>>(SCORE, k1, k2, N2, P2i, V2); }
    { dim3 g((k2 + 255) / 256, k2); k_gatherA<<<g, 256>>>(B1, k1, P2i, A2, k2); }
    k_gatherX<<<(k2 * Hdim + 255) / 256, 256>>>(X1, Hdim, P2i, V2, HP, k2);
    h_gcn(A2, k2, HP, Hdim, w2, Hdim, b2, X2, 1, 1, Y, Z, ACC, ZH, ZL, DINV, CORR);

    // augment(A2) -> B2 (dense, tf32; MS2 entries are integers ~<=few hundred -> exact)
    k_copy_addI<<<4096, 256>>>(A2, MS, k2);
    h_mma(B2, MS, MS, k2, k2, k2, 0);
    k_zero_diag<<<(k2 + 255) / 256, 256>>>(B2, k2);

    // pool3
    k_score<<<k2, 64>>>(X2, p3, SCORE);
    { int N2 = 1; while (N2 < k2) N2 <<= 1;
      k_topsort<<<1, 1024>>>(SCORE, k2, k3, N2, P3i, V3); }
    { dim3 g((k3 + 255) / 256, k3); k_gatherA<<<g, 256>>>(B2, k2, P3i, A3, k3); }
    k_gatherX<<<(k3 * Hdim + 255) / 256, 256>>>(X2, Hdim, P3i, V3, HP, k3);
    // A3 entries can exceed 2048 (not tf32-exact) -> fp32 path; tiny anyway
    h_gcn(A3, k3, HP, Hdim, w3, Hdim, b3, X3, 1, 0, Y, Z, ACC, ZH, ZL, DINV, CORR);

    // ---- up path ----
    k_copy<<<1024, 256>>>(HA, X2, (size_t)k2 * Hdim);
    k_scatadd<<<(k3 * Hdim + 255) / 256, 256>>>(HA, P3i, X3, k3, Hdim);
    h_gcn(A2, k2, HA, Hdim, uw0, Hdim, ub0, HB, 1, 1, Y, Z, ACC, ZH, ZL, DINV, CORR);

    k_copy<<<1024, 256>>>(HA, X1, (size_t)k1 * Hdim);
    k_scatadd<<<(k2 * Hdim + 255) / 256, 256>>>(HA, P2i, HB, k2, Hdim);
    h_gcn(A1, k1, HA, Hdim, uw1, Hdim, ub1, HP, 1, 1, Y, Z, ACC, ZH, ZL, DINV, CORR);

    k_copy<<<1024, 256>>>(HA, X0, (size_t)N * Hdim);
    k_scatadd<<<(k1 * Hdim + 255) / 256, 256>>>(HA, P1i, HP, k1, Hdim);
    h_gcn(A0, N, HA, Hdim, uw2, OUT, ub2, HOUTp, 0, 1, Y, Z, ACC, ZH, ZL, DINV, CORR);

    // ---- layernorm + residual ----
    k_ln<<<N, OUT>>>(HOUTp, ln_g, ln_b, U, OUT);
    h_gemm(RESID, U, res_w, N, OUT, OUT, res_b);

    // ---- GAT layers (sparse attention over mask rows) ----
    k_nbr<<<N, 128>>>(A0, N, NBC, NBL);

    h_gemm(HF, U, g1w, N, HEADS * OUT, OUT, nullptr);
    { dim3 g(N, HEADS); k_attcoef<<<g, OUT>>>(HF, HEADS, OUT, g1as, g1ad, ES, ED); }
    k_gatattn<<<N, 128>>>(HF, ES, ED, NBC, NBL, g1b, nullptr, G1, HEADS, OUT, 1);

    h_gemm(Y, G1, g2w, N, OUT, HEADS * OUT, nullptr);
    { dim3 g(N, 1); k_attcoef<<<g, OUT>>>(Y, 1, OUT, g2as, g2ad, ES, ED); }
    k_gatattn<<<N, 128>>>(Y, ES, ED, NBC, NBL, g2b, RESID, (float*)d_out, 1, OUT, 0);
}

// round 7
// speedup vs baseline: 2.3035x; 2.3035x over previous
#include <cuda_runtime.h>
#include <math.h>
#include <float.h>
#include <stdint.h>

#define MAXN 4096
#define MAXE 65536
#define MAXD 128   // max distinct neighbors per destination (Poisson(16) tail ~0 beyond 100)

// ------------------------- device scratch (module-allocated, no cudaMalloc) -------------------------
__device__ float dA0[(size_t)MAXN * MAXN];       // 67 MB
__device__ float dB0[(size_t)MAXN * MAXN];       // 67 MB  (augment(A0))
__device__ float dA1[2048 * 2048];
__device__ float dB1[2048 * 2048];
__device__ float dMS[2048 * 2048];               // M = A + I scratch for dense augment
__device__ float dA2[1024 * 1024];
__device__ float dB2[1024 * 1024];
__device__ float dA3[512 * 512];

__device__ float dY[(size_t)MAXN * 128];
__device__ float dZ[(size_t)MAXN * 128];
__device__ float dACC[(size_t)MAXN * 128];

__device__ float dX0[(size_t)MAXN * 64];
__device__ float dX1[2048 * 64];
__device__ float dX2[1024 * 64];
__device__ float dX3[512 * 64];
__device__ float dHP[(size_t)MAXN * 64];         // pooled-x / up intermediate
__device__ float dHA[(size_t)MAXN * 64];         // up-path ping
__device__ float dHB[(size_t)MAXN * 64];         // up-path pong
__device__ float dHOUT[(size_t)MAXN * 128];
__device__ float dU[(size_t)MAXN * 128];
__device__ float dRESID[(size_t)MAXN * 128];
__device__ float dHF[(size_t)MAXN * 512];        // GAT1 transformed features
__device__ float dG1[(size_t)MAXN * 512];        // GAT1 output

__device__ float dES[(size_t)MAXN * 4];
__device__ float dED[(size_t)MAXN * 4];
__device__ float dScore[MAXN];
__device__ int   dPerm1[2048];
__device__ int   dPerm2[1024];
__device__ int   dPerm3[512];
__device__ float dVals1[2048];
__device__ float dVals2[1024];
__device__ float dVals3[512];
__device__ float dDinv[MAXN];
__device__ float dCorr[MAXN];

__device__ int dCntS[MAXN], dCntD[MAXN];
__device__ int dSelf[MAXN];
__device__ int dOffS[MAXN + 1], dOffD[MAXN + 1];
__device__ int dFillS[MAXN], dFillD[MAXN];
__device__ int dLstS[MAXE], dLstD[MAXE];
__device__ int dNbrCnt[MAXN];
__device__ int dNbrLst[(size_t)MAXN * MAXD];

// ------------------------- small helpers -------------------------
__device__ __forceinline__ float lrelu(float x) { return x > 0.f ? x : 0.2f * x; }

// one kernel zeroes everything needed at the start (also shifts ncu's -s 5 window
// onto a real kernel instead of a 3us memset)
__global__ void k_zero_all(float* A0, float* B0, size_t nf,
                           int* c0, int* c1, int* c2, int* c3, int* c4, int n) {
    size_t i = (size_t)blockIdx.x * blockDim.x + threadIdx.x;
    size_t stride = (size_t)gridDim.x * blockDim.x;
    for (size_t j = i; j < nf; j += stride) { A0[j] = 0.f; B0[j] = 0.f; }
    for (size_t j = i; j < (size_t)n; j += stride) {
        c0[j] = 0; c1[j] = 0; c2[j] = 0; c3[j] = 0; c4[j] = 0;
    }
}

// build A0 (dense), per-node degree counts, self-loop counts
__global__ void k_build_a0(const int* ei, int E, int n, float* A,
                           int* cntS, int* cntD, int* selfc) {
    int e = blockIdx.x * blockDim.x + threadIdx.x;
    if (e >= E) return;
    int s = ei[e], d = ei[E + e];
    atomicAdd(&A[(size_t)d * n + s], 1.f);
    atomicAdd(&cntS[s], 1);
    atomicAdd(&cntD[d], 1);
    if (s == d) atomicAdd(&selfc[d], 1);
}

// two scans in one launch (block 0: S, block 1: D)
__global__ void k_scan2(const int* cntS, int* offS, const int* cntD, int* offD, int n) {
    __shared__ int ps[1024];
    const int* cnt = blockIdx.x == 0 ? cntS : cntD;
    int* off = blockIdx.x == 0 ? offS : offD;
    int t = threadIdx.x;
    int chunk = (n + 1023) >> 10;
    int base = t * chunk;
    int s = 0;
    for (int j = 0; j < chunk; j++) { int idx = base + j; if (idx < n) s += cnt[idx]; }
    ps[t] = s; __syncthreads();
    for (int d = 1; d < 1024; d <<= 1) {
        int v = (t >= d) ? ps[t - d] : 0;
        __syncthreads();
        ps[t] += v;
        __syncthreads();
    }
    int run = (t > 0) ? ps[t - 1] : 0;
    if (t == 0) off[0] = 0;
    for (int j = 0; j < chunk; j++) {
        int idx = base + j;
        if (idx < n) { run += cnt[idx]; off[idx + 1] = run; }
    }
}

__global__ void k_csr_fill(const int* ei, int E, const int* offS, const int* offD,
                           int* fillS, int* fillD, int* lstS, int* lstD) {
    int e = blockIdx.x * blockDim.x + threadIdx.x;
    if (e >= E) return;
    int s = ei[e], d = ei[E + e];
    int pS = atomicAdd(&fillS[s], 1);
    lstS[offS[s] + pS] = d;
    int pD = atomicAdd(&fillD[d], 1);
    lstD[offD[d] + pD] = s;
}

__global__ void k_add_2a(const int* ei, int E, int n, float* C) {
    int e = blockIdx.x * blockDim.x + threadIdx.x;
    if (e >= E) return;
    int s = ei[e], d = ei[E + e];
    atomicAdd(&C[(size_t)d * n + s], 2.f);
}

// C += A0 @ A0 via 2-path pair enumeration: edge(j->k) x edge(k->i) => C[i,j]+=1
__global__ void k_spgemm_pairs(const int* cntS, const int* cntD, const int* offS, const int* offD,
                               const int* lstS, const int* lstD, float* C, int n) {
    int k = blockIdx.x;
    int ni = cntS[k], nj = cntD[k];
    long tot = (long)ni * nj;
    int oS = offS[k], oD = offD[k];
    for (long p = threadIdx.x; p < tot; p += blockDim.x) {
        int i = lstS[oS + (int)(p / nj)];
        int j = lstD[oD + (int)(p % nj)];
        atomicAdd(&C[(size_t)i * n + j], 1.f);
    }
}

__global__ void k_zero_diag(float* C, int n) {
    int i = blockIdx.x * blockDim.x + threadIdx.x;
    if (i < n) C[(size_t)i * n + i] = 0.f;
}

__global__ void k_copy_addI(const float* A, float* M, int n) {
    size_t idx = (size_t)blockIdx.x * blockDim.x + threadIdx.x;
    size_t tot = (size_t)n * n;
    size_t stride = (size_t)gridDim.x * blockDim.x;
    for (; idx < tot; idx += stride) {
        int i = (int)(idx / n), j = (int)(idx % n);
        M[idx] = A[idx] + (i == j ? 1.f : 0.f);
    }
}

// ------------------------- SGEMM: C[M,N] = A[M,K] @ B[K,N] (+bias per col) -------------------------
__global__ void k_gemm(const float* __restrict__ A, const float* __restrict__ B,
                       float* __restrict__ C, int M, int N, int K,
                       const float* __restrict__ bias) {
    __shared__ float As[16][64];
    __shared__ float Bs[16][64];
    int tid = threadIdx.x;
    int tx = tid & 15, ty = tid >> 4;
    int bm = blockIdx.y * 64, bn = blockIdx.x * 64;
    float acc[4][4] = {};
    for (int k0 = 0; k0 < K; k0 += 16) {
#pragma unroll
        for (int l = 0; l < 4; l++) {
            int e = tid + l * 256;
            int mm = e >> 4, kk = e & 15;
            int gr = bm + mm, gc = k0 + kk;
            As[kk][mm] = (gr < M && gc < K) ? A[(size_t)gr * K + gc] : 0.f;
        }
#pragma unroll
        for (int l = 0; l < 4; l++) {
            int e = tid + l * 256;
            int kk = e >> 6, nn = e & 63;
            int gr = k0 + kk, gc = bn + nn;
            Bs[kk][nn] = (gr < K && gc < N) ? B[(size_t)gr * N + gc] : 0.f;
        }
        __syncthreads();
#pragma unroll
        for (int kk = 0; kk < 16; kk++) {
            float a[4], b[4];
#pragma unroll
            for (int i = 0; i < 4; i++) a[i] = As[kk][ty * 4 + i];
#pragma unroll
            for (int j = 0; j < 4; j++) b[j] = Bs[kk][tx * 4 + j];
#pragma unroll
            for (int i = 0; i < 4; i++)
#pragma unroll
                for (int j = 0; j < 4; j++) acc[i][j] += a[i] * b[j];
        }
        __syncthreads();
    }
#pragma unroll
    for (int i = 0; i < 4; i++) {
        int r = bm + ty * 4 + i;
        if (r >= M) continue;
#pragma unroll
        for (int j = 0; j < 4; j++) {
            int c = bn + tx * 4 + j;
            if (c >= N) continue;
            float v = acc[i][j];
            if (bias) v += bias[c];
            C[(size_t)r * N + c] = v;
        }
    }
}

// ------------------------- TF32 tensor-core GEMM (square augment GEMMs only) ----------------------
__device__ __forceinline__ void mma_tf32_op(float* c, const uint32_t* a, const uint32_t* b) {
    asm volatile(
        "mma.sync.aligned.m16n8k8.row.col.f32.tf32.tf32.f32 "
        "{%0,%1,%2,%3}, {%4,%5,%6,%7}, {%8,%9}, {%0,%1,%2,%3};"
        : "+f"(c[0]), "+f"(c[1]), "+f"(c[2]), "+f"(c[3])
        : "r"(a[0]), "r"(a[1]), "r"(a[2]), "r"(a[3]), "r"(b[0]), "r"(b[1]));
}

__global__ void __launch_bounds__(256)
k_mma_tf32(const float* __restrict__ A, const float* __restrict__ B,
           float* __restrict__ C, int M, int N, int K) {
    __shared__ float As[128][36];   // [m][k], stride-36 pad: conflict-free frag loads
    __shared__ float Bs[128][36];   // [n][k]
    int tid = threadIdx.x;
    int lane = tid & 31, warp = tid >> 5;
    int wm = warp >> 2, wn = warp & 3;             // 2 x 4 warp grid (64x32 per warp)
    int g = lane >> 2, tg = lane & 3;
    int bm = blockIdx.y * 128, bn = blockIdx.x * 128;
    float acc[4][4][4] = {};

    for (int k0 = 0; k0 < K; k0 += 32) {
        // A tile: 128 rows x 32 cols, float4 coalesced along K
#pragma unroll
        for (int i = 0; i < 4; i++) {
            int flat = tid + i * 256;
            int r = flat >> 3, c4 = (flat & 7) * 4;
            float4 v = make_float4(0.f, 0.f, 0.f, 0.f);
            if (bm + r < M) v = *(const float4*)&A[(size_t)(bm + r) * K + k0 + c4];
            *(float4*)&As[r][c4] = v;
        }
        // B tile: 32 rows (k) x 128 cols (n), transpose into [n][k]
#pragma unroll
        for (int i = 0; i < 4; i++) {
            int flat = tid + i * 256;
            int kr = flat >> 5, c4 = (flat & 31) * 4;
            float v0 = 0.f, v1 = 0.f, v2 = 0.f, v3 = 0.f;
            if (bn + c4 + 3 < N) {
                float4 v = *(const float4*)&B[(size_t)(k0 + kr) * N + bn + c4];
                v0 = v.x; v1 = v.y; v2 = v.z; v3 = v.w;
            } else {
                const float* bp = &B[(size_t)(k0 + kr) * N];
                if (bn + c4 + 0 < N) v0 = bp[bn + c4 + 0];
                if (bn + c4 + 1 < N) v1 = bp[bn + c4 + 1];
                if (bn + c4 + 2 < N) v2 = bp[bn + c4 + 2];
                if (bn + c4 + 3 < N) v3 = bp[bn + c4 + 3];
            }
            Bs[c4 + 0][kr] = v0; Bs[c4 + 1][kr] = v1;
            Bs[c4 + 2][kr] = v2; Bs[c4 + 3][kr] = v3;
        }
        __syncthreads();
#pragma unroll
        for (int ks = 0; ks < 32; ks += 8) {
            uint32_t af[4][4], bf[4][2];
#pragma unroll
            for (int mt = 0; mt < 4; mt++) {
                int m = wm * 64 + mt * 16;
                af[mt][0] = __float_as_uint(As[m + g][ks + tg]);
                af[mt][1] = __float_as_uint(As[m + g + 8][ks + tg]);
                af[mt][2] = __float_as_uint(As[m + g][ks + tg + 4]);
                af[mt][3] = __float_as_uint(As[m + g + 8][ks + tg + 4]);
            }
#pragma unroll
            for (int nt = 0; nt < 4; nt++) {
                int n = wn * 32 + nt * 8;
                bf[nt][0] = __float_as_uint(Bs[n + g][ks + tg]);
                bf[nt][1] = __float_as_uint(Bs[n + g][ks + tg + 4]);
            }
#pragma unroll
            for (int mt = 0; mt < 4; mt++)
#pragma unroll
                for (int nt = 0; nt < 4; nt++)
                    mma_tf32_op(acc[mt][nt], af[mt], bf[nt]);
        }
        __syncthreads();
    }
    // epilogue
#pragma unroll
    for (int mt = 0; mt < 4; mt++) {
#pragma unroll
        for (int nt = 0; nt < 4; nt++) {
            int row0 = bm + wm * 64 + mt * 16 + g;
            int col = bn + wn * 32 + nt * 8 + tg * 2;
            float* c = acc[mt][nt];
            if (row0 < M) {
                float* p = &C[(size_t)row0 * N];
                if (col < N)     p[col]     = c[0];
                if (col + 1 < N) p[col + 1] = c[1];
            }
            int row1 = row0 + 8;
            if (row1 < M) {
                float* p = &C[(size_t)row1 * N];
                if (col < N)     p[col]     = c[2];
                if (col + 1 < N) p[col + 1] = c[3];
            }
        }
    }
}

// ------------------------- GCN pieces -------------------------
__global__ void k_rowstats(const float* A, int n, float* dinv, float* corr) {
    int r = blockIdx.x, t = threadIdx.x;
    __shared__ float sh[256];
    float s = 0.f;
    for (int j = t; j < n; j += 256) s += A[(size_t)r * n + j];
    sh[t] = s; __syncthreads();
    for (int st = 128; st > 0; st >>= 1) { if (t < st) sh[t] += sh[t + st]; __syncthreads(); }
    if (t == 0) {
        float diag = A[(size_t)r * n + r];
        float ex = (diag == 0.f) ? 2.f : 0.f;
        dinv[r] = 1.f / sqrtf(sh[0] + ex);
        corr[r] = ex;
    }
}

// A0 rowstats straight from CSR counts (rowsum == in-degree incl. duplicates)
__global__ void k_rowstats_csr(const int* cntD, const int* selfc, float* dinv, float* corr, int n) {
    int d = blockIdx.x * blockDim.x + threadIdx.x;
    if (d >= n) return;
    float ex = (selfc[d] == 0) ? 2.f : 0.f;
    dinv[d] = 1.f / sqrtf((float)cntD[d] + ex);
    corr[d] = ex;
}

__global__ void k_scale_rows(const float* Y, const float* dinv, float* Z, int n, int F) {
    size_t idx = (size_t)blockIdx.x * blockDim.x + threadIdx.x;
    if (idx >= (size_t)n * F) return;
    Z[idx] = dinv[idx / F] * Y[idx];
}

// sparse propagation: ACC[d,:] = sum over incoming edges of Z[src,:]
// (duplicate edges appear multiple times in lstD == weighted sum, exact)
__global__ void k_spmm(const int* __restrict__ offD, const int* __restrict__ lstD,
                       const float* __restrict__ Z, float* __restrict__ ACC, int F) {
    int d = blockIdx.x, f = threadIdx.x;
    int b = offD[d], e = offD[d + 1];
    float acc = 0.f;
    for (int i = b; i < e; i++) acc += Z[(size_t)lstD[i] * F + f];
    ACC[(size_t)d * F + f] = acc;
}

__global__ void k_gcn_epi(const float* ACC, const float* Z, const float* dinv, const float* corr,
                          const float* b, float* out, int n, int F, int relu) {
    size_t idx = (size_t)blockIdx.x * blockDim.x + threadIdx.x;
    if (idx >= (size_t)n * F) return;
    int i = (int)(idx / F), f = (int)(idx % F);
    float v = dinv[i] * (ACC[idx] + corr[i] * Z[idx]) + b[f];
    if (relu) v = fmaxf(v, 0.f);
    out[idx] = v;
}

// ------------------------- pooling -------------------------
__global__ void k_score(const float* x, const float* p, float* score) { // F = 64, block 64
    int i = blockIdx.x, t = threadIdx.x;
    __shared__ float s1[64], s2[64];
    float xv = x[(size_t)i * 64 + t], pv = p[t];
    s1[t] = xv * pv; s2[t] = pv * pv; __syncthreads();
    for (int st = 32; st > 0; st >>= 1) {
        if (t < st) { s1[t] += s1[t + st]; s2[t] += s2[t + st]; }
        __syncthreads();
    }
    if (t == 0) score[i] = tanhf(s1[0] / sqrtf(s2[0]));
}

__global__ void k_topsort(const float* score, int n, int k, int N2, int* perm, float* vals) {
    __shared__ float sv[4096];
    __shared__ int si[4096];
    int t = threadIdx.x;
    for (int i = t; i < N2; i += blockDim.x) {
        if (i < n) { sv[i] = score[i]; si[i] = i; }
        else       { sv[i] = -FLT_MAX; si[i] = 0x3fffffff; }
    }
    __syncthreads();
    for (int size = 2; size <= N2; size <<= 1) {
        for (int stride = size >> 1; stride > 0; stride >>= 1) {
            for (int i = t; i < N2; i += blockDim.x) {
                int j = i ^ stride;
                if (j > i) {
                    float av = sv[i]; int ai = si[i];
                    float bv = sv[j]; int bi = si[j];
                    bool before = (av > bv) || (av == bv && ai < bi); // descending, stable
                    bool desc = ((i & size) == 0);
                    if (desc != before) { sv[i] = bv; si[i] = bi; sv[j] = av; si[j] = ai; }
                }
            }
            __syncthreads();
        }
    }
    for (int i = t; i < k; i += blockDim.x) { perm[i] = si[i]; vals[i] = sv[i]; }
}

__global__ void k_gatherA(const float* B, int ldB, const int* perm, float* Aout, int k) {
    int j = blockIdx.x * blockDim.x + threadIdx.x;
    int i = blockIdx.y;
    if (i < k && j < k) Aout[(size_t)i * k + j] = B[(size_t)perm[i] * ldB + perm[j]];
}

__global__ void k_gatherX(const float* X, int F, const int* perm, const float* vals, float* out, int k) {
    size_t idx = (size_t)blockIdx.x * blockDim.x + threadIdx.x;
    if (idx >= (size_t)k * F) return;
    int i = (int)(idx / F), f = (int)(idx % F);
    out[idx] = X[(size_t)perm[i] * F + f] * vals[i];
}

__global__ void k_copy(float* dst, const float* src, size_t n) {
    size_t i = (size_t)blockIdx.x * blockDim.x + threadIdx.x;
    size_t stride = (size_t)gridDim.x * blockDim.x;
    for (; i < n; i += stride) dst[i] = src[i];
}

__global__ void k_scatadd(float* h, const int* perm, const float* xl, int k, int F) {
    size_t idx = (size_t)blockIdx.x * blockDim.x + threadIdx.x;
    if (idx >= (size_t)k * F) return;
    int t = (int)(idx / F), f = (int)(idx % F);
    h[(size_t)perm[t] * F + f] += xl[idx];
}

// ------------------------- layernorm -------------------------
__global__ void k_ln(const float* h, const float* g, const float* b, float* u, int F) { // block = F = 128
    int row = blockIdx.x, t = threadIdx.x;
    __shared__ float sh[128];
    float v = h[(size_t)row * F + t];
    sh[t] = v; __syncthreads();
    for (int st = 64; st > 0; st >>= 1) { if (t < st) sh[t] += sh[t + st]; __syncthreads(); }
    float mu = sh[0] / F;
    __syncthreads();
    float dv = v - mu;
    sh[t] = dv * dv; __syncthreads();
    for (int st = 64; st > 0; st >>= 1) { if (t < st) sh[t] += sh[t + st]; __syncthreads(); }
    float var = sh[0] / F;
    u[(size_t)row * F + t] = dv * rsqrtf(var + 1e-6f) * g[t] + b[t];
}

// ------------------------- GAT -------------------------
__global__ void k_nbr(const float* A, int n, int* cnt, int* lst) { // block 128
    int d = blockIdx.x, t = threadIdx.x;
    int chunk = (n + 127) >> 7;
    int s0 = t * chunk;
    int c = 0;
    for (int j = 0; j < chunk; j++) {
        int s = s0 + j;
        if (s < n && (A[(size_t)d * n + s] > 0.f || s == d)) c++;
    }
    __shared__ int sc[128];
    sc[t] = c; __syncthreads();
    if (t == 0) {
        int run = 0;
        for (int i = 0; i < 128; i++) { int v = sc[i]; sc[i] = run; run += v; }
        cnt[d] = run > MAXD ? MAXD : run;
    }
    __syncthreads();
    int off = sc[t];
    for (int j = 0; j < chunk; j++) {
        int s = s0 + j;
        if (s < n && (A[(size_t)d * n + s] > 0.f || s == d)) {
            if (off < MAXD) lst[(size_t)d * MAXD + off] = s;
            off++;
        }
    }
}

__global__ void k_attcoef(const float* hf, int H, int C, const float* asrc, const float* adst,
                          float* es, float* ed) { // grid (n, H), block C=128
    int s = blockIdx.x, h = blockIdx.y, t = threadIdx.x;
    __shared__ float s1[128], s2[128];
    float x = hf[(size_t)s * H * C + h * C + t];
    s1[t] = x * asrc[h * C + t];
    s2[t] = x * adst[h * C + t];
    __syncthreads();
    for (int st = 64; st > 0; st >>= 1) {
        if (t < st) { s1[t] += s1[t + st]; s2[t] += s2[t + st]; }
        __syncthreads();
    }
    if (t == 0) { es[s * H + h] = s1[0]; ed[s * H + h] = s2[0]; }
}

__global__ void k_gatattn(const float* hf, const float* es, const float* ed,
                          const int* cnt, const int* lst, const float* bias,
                          const float* resid, float* out, int H, int C, int doElu) { // block 128
    int d = blockIdx.x, t = threadIdx.x;
    __shared__ int snb[MAXD];
    __shared__ float sw[MAXD];
    __shared__ float sred[128];
    int m = cnt[d];
    if (t < m) snb[t] = lst[(size_t)d * MAXD + t];
    __syncthreads();
    for (int h = 0; h < H; h++) {
        float edv = ed[d * H + h];
        float mx = -FLT_MAX;
        for (int i = t; i < m; i += 128) mx = fmaxf(mx, lrelu(edv + es[snb[i] * H + h]));
        sred[t] = mx; __syncthreads();
        for (int st = 64; st > 0; st >>= 1) { if (t < st) sred[t] = fmaxf(sred[t], sred[t + st]); __syncthreads(); }
        float M = sred[0];
        __syncthreads();
        float dp = 0.f;
        for (int i = t; i < m; i += 128) {
            float w = expf(lrelu(edv + es[snb[i] * H + h]) - M);
            sw[i] = w; dp += w;
        }
        sred[t] = dp; __syncthreads();
        for (int st = 64; st > 0; st >>= 1) { if (t < st) sred[t] += sred[t + st]; __syncthreads(); }
        float den = sred[0];
        __syncthreads();
        float num = 0.f;
        for (int i = 0; i < m; i++) num += sw[i] * hf[(size_t)snb[i] * H * C + h * C + t];
        float o = num / den + bias[h * C + t];
        if (doElu) o = o > 0.f ? o : (expf(o) - 1.f);
        if (resid) o += resid[(size_t)d * C + t];
        out[(size_t)d * H * C + h * C + t] = o;
        __syncthreads();
    }
}

// ------------------------- host orchestration -------------------------
static void h_gemm(float* C, const float* A, const float* B, int M, int N, int K, const float* bias) {
    dim3 g((N + 63) / 64, (M + 63) / 64);
    k_gemm<<<g, 256>>>(A, B, C, M, N, K, bias);
}

static void h_mma(float* C, const float* A, const float* B, int M, int N, int K) {
    dim3 g((N + 127) / 128, (M + 127) / 128);
    k_mma_tf32<<<g, 256>>>(A, B, C, M, N, K);
}

// dense GCN (levels 1..3): fp32 SGEMM propagation
static void h_gcn(const float* A, int n, const float* x, int Fin, const float* W, int Fout,
                  const float* bias, float* out, int relu,
                  float* Y, float* Z, float* ACC, float* dinv, float* corr) {
    h_gemm(Y, x, W, n, Fout, Fin, nullptr);                     // Y = x @ W
    k_rowstats<<<n, 256>>>(A, n, dinv, corr);
    int tot = n * Fout;
    k_scale_rows<<<(tot + 255) / 256, 256>>>(Y, dinv, Z, n, Fout);
    h_gemm(ACC, A, Z, n, Fout, n, nullptr);                     // ACC = A @ Z
    k_gcn_epi<<<(tot + 255) / 256, 256>>>(ACC, Z, dinv, corr, bias, out, n, Fout, relu);
}

// sparse GCN for level 0 (A0 CSR): SpMM propagation, CSR rowstats
static void h_gcn0(const int* offD, const int* lstD, const int* cntD, const int* selfc,
                   int n, const float* x, int Fin, const float* W, int Fout,
                   const float* bias, float* out, int relu,
                   float* Y, float* Z, float* ACC, float* dinv, float* corr) {
    h_gemm(Y, x, W, n, Fout, Fin, nullptr);
    k_rowstats_csr<<<(n + 255) / 256, 256>>>(cntD, selfc, dinv, corr, n);
    int tot = n * Fout;
    k_scale_rows<<<(tot + 255) / 256, 256>>>(Y, dinv, Z, n, Fout);
    k_spmm<<<n, Fout>>>(offD, lstD, Z, ACC, Fout);
    k_gcn_epi<<<(tot + 255) / 256, 256>>>(ACC, Z, dinv, corr, bias, out, n, Fout, relu);
}

extern "C" void kernel_launch(void* const* d_in, const int* in_sizes, int n_in,
                              void* d_out, int out_size) {
    const float* x        = (const float*)d_in[0];
    const int*   ei       = (const int*)d_in[1];
    const float* w0 = (const float*)d_in[2];  const float* b0 = (const float*)d_in[3];
    const float* w1 = (const float*)d_in[4];  const float* b1 = (const float*)d_in[5];
    const float* w2 = (const float*)d_in[6];  const float* b2 = (const float*)d_in[7];
    const float* w3 = (const float*)d_in[8];  const float* b3 = (const float*)d_in[9];
    const float* p1 = (const float*)d_in[10]; const float* p2 = (const float*)d_in[11];
    const float* p3 = (const float*)d_in[12];
    const float* uw0 = (const float*)d_in[13]; const float* ub0 = (const float*)d_in[14];
    const float* uw1 = (const float*)d_in[15]; const float* ub1 = (const float*)d_in[16];
    const float* uw2 = (const float*)d_in[17]; const float* ub2 = (const float*)d_in[18];
    const float* ln_g = (const float*)d_in[19]; const float* ln_b = (const float*)d_in[20];
    const float* res_w = (const float*)d_in[21]; const float* res_b = (const float*)d_in[22];
    const float* g1w = (const float*)d_in[23];
    const float* g1as = (const float*)d_in[24]; const float* g1ad = (const float*)d_in[25];
    const float* g1b = (const float*)d_in[26];
    const float* g2w = (const float*)d_in[27];
    const float* g2as = (const float*)d_in[28]; const float* g2ad = (const float*)d_in[29];
    const float* g2b = (const float*)d_in[30];

    int Hdim  = in_sizes[3];                 // 64
    int INF   = in_sizes[2] / Hdim;          // 3
    int N     = in_sizes[0] / INF;           // 4096
    int E     = in_sizes[1] / 2;             // 65536
    int OUT   = in_sizes[18];                // 128
    int HEADS = in_sizes[26] / OUT;          // 4

    // fetch device-symbol addresses
    float *A0, *B0, *A1, *B1, *MS, *A2, *B2, *A3;
    float *Y, *Z, *ACC, *X0, *X1, *X2, *X3, *HP, *HA, *HB, *HOUTp, *U, *RESID, *HF, *G1;
    float *ES, *ED, *SCORE, *V1, *V2, *V3, *DINV, *CORR;
    int *P1i, *P2i, *P3i, *CNTS, *CNTD, *SELF, *OFFS, *OFFD, *FILLS, *FILLD, *LSTS, *LSTD, *NBC, *NBL;
    cudaGetSymbolAddress((void**)&A0, dA0);   cudaGetSymbolAddress((void**)&B0, dB0);
    cudaGetSymbolAddress((void**)&A1, dA1);   cudaGetSymbolAddress((void**)&B1, dB1);
    cudaGetSymbolAddress((void**)&MS, dMS);   cudaGetSymbolAddress((void**)&A2, dA2);
    cudaGetSymbolAddress((void**)&B2, dB2);   cudaGetSymbolAddress((void**)&A3, dA3);
    cudaGetSymbolAddress((void**)&Y, dY);     cudaGetSymbolAddress((void**)&Z, dZ);
    cudaGetSymbolAddress((void**)&ACC, dACC);
    cudaGetSymbolAddress((void**)&X0, dX0);
    cudaGetSymbolAddress((void**)&X1, dX1);   cudaGetSymbolAddress((void**)&X2, dX2);
    cudaGetSymbolAddress((void**)&X3, dX3);   cudaGetSymbolAddress((void**)&HP, dHP);
    cudaGetSymbolAddress((void**)&HA, dHA);   cudaGetSymbolAddress((void**)&HB, dHB);
    cudaGetSymbolAddress((void**)&HOUTp, dHOUT); cudaGetSymbolAddress((void**)&U, dU);
    cudaGetSymbolAddress((void**)&RESID, dRESID); cudaGetSymbolAddress((void**)&HF, dHF);
    cudaGetSymbolAddress((void**)&G1, dG1);
    cudaGetSymbolAddress((void**)&ES, dES);   cudaGetSymbolAddress((void**)&ED, dED);
    cudaGetSymbolAddress((void**)&SCORE, dScore);
    cudaGetSymbolAddress((void**)&P1i, dPerm1); cudaGetSymbolAddress((void**)&P2i, dPerm2);
    cudaGetSymbolAddress((void**)&P3i, dPerm3);
    cudaGetSymbolAddress((void**)&V1, dVals1); cudaGetSymbolAddress((void**)&V2, dVals2);
    cudaGetSymbolAddress((void**)&V3, dVals3);
    cudaGetSymbolAddress((void**)&DINV, dDinv); cudaGetSymbolAddress((void**)&CORR, dCorr);
    cudaGetSymbolAddress((void**)&CNTS, dCntS); cudaGetSymbolAddress((void**)&CNTD, dCntD);
    cudaGetSymbolAddress((void**)&SELF, dSelf);
    cudaGetSymbolAddress((void**)&OFFS, dOffS); cudaGetSymbolAddress((void**)&OFFD, dOffD);
    cudaGetSymbolAddress((void**)&FILLS, dFillS); cudaGetSymbolAddress((void**)&FILLD, dFillD);
    cudaGetSymbolAddress((void**)&LSTS, dLstS); cudaGetSymbolAddress((void**)&LSTD, dLstD);
    cudaGetSymbolAddress((void**)&NBC, dNbrCnt); cudaGetSymbolAddress((void**)&NBL, dNbrLst);

    int k1 = (N + 1) / 2, k2 = (k1 + 1) / 2, k3 = (k2 + 1) / 2;

    // ---- build A0 (dense + CSR) and augment(A0)=B0 via sparse 2-paths ----
    k_zero_all<<<4096, 256>>>(A0, B0, (size_t)N * N, CNTS, CNTD, FILLS, FILLD, SELF, N);
    k_build_a0<<<(E + 255) / 256, 256>>>(ei, E, N, A0, CNTS, CNTD, SELF);
    k_scan2<<<2, 1024>>>(CNTS, OFFS, CNTD, OFFD, N);
    k_csr_fill<<<(E + 255) / 256, 256>>>(ei, E, OFFS, OFFD, FILLS, FILLD, LSTS, LSTD);
    k_add_2a<<<(E + 255) / 256, 256>>>(ei, E, N, B0);
    k_spgemm_pairs<<<N, 256>>>(CNTS, CNTD, OFFS, OFFD, LSTS, LSTD, B0, N);
    k_zero_diag<<<(N + 255) / 256, 256>>>(B0, N);

    // ---- down path ----
    h_gcn0(OFFD, LSTD, CNTD, SELF, N, x, INF, w0, Hdim, b0, X0, 1, Y, Z, ACC, DINV, CORR);

    // pool1 (from B0)
    k_score<<<N, 64>>>(X0, p1, SCORE);
    { int N2 = 1; while (N2 < N) N2 <<= 1;
      k_topsort<<<1, 1024>>>(SCORE, N, k1, N2, P1i, V1); }
    { dim3 g((k1 + 255) / 256, k1); k_gatherA<<<g, 256>>>(B0, N, P1i, A1, k1); }
    k_gatherX<<<(k1 * Hdim + 255) / 256, 256>>>(X0, Hdim, P1i, V1, HP, k1);
    h_gcn(A1, k1, HP, Hdim, w1, Hdim, b1, X1, 1, Y, Z, ACC, DINV, CORR);

    // augment(A1) -> B1 (dense, tf32 tensor cores; MS holds small integers -> exact)
    k_copy_addI<<<4096, 256>>>(A1, MS, k1);
    h_mma(B1, MS, MS, k1, k1, k1);
    k_zero_diag<<<(k1 + 255) / 256, 256>>>(B1, k1);

    // pool2
    k_score<<<k1, 64>>>(X1, p2, SCORE);
    { int N2 = 1; while (N2 < k1) N2 <<= 1;
      k_topsort<<<1, 1024>>>(SCORE, k1, k2, N2, P2i, V2); }
    { dim3 g((k2 + 255) / 256, k2); k_gatherA<<<g, 256>>>(B1, k1, P2i, A2, k2); }
    k_gatherX<<<(k2 * Hdim + 255) / 256, 256>>>(X1, Hdim, P2i, V2, HP, k2);
    h_gcn(A2, k2, HP, Hdim, w2, Hdim, b2, X2, 1, Y, Z, ACC, DINV, CORR);

    // augment(A2) -> B2 (dense, tf32; entries are integers <= ~2048 -> exact)
    k_copy_addI<<<4096, 256>>>(A2, MS, k2);
    h_mma(B2, MS, MS, k2, k2, k2);
    k_zero_diag<<<(k2 + 255) / 256, 256>>>(B2, k2);

    // pool3
    k_score<<<k2, 64>>>(X2, p3, SCORE);
    { int N2 = 1; while (N2 < k2) N2 <<= 1;
      k_topsort<<<1, 1024>>>(SCORE, k2, k3, N2, P3i, V3); }
    { dim3 g((k3 + 255) / 256, k3); k_gatherA<<<g, 256>>>(B2, k2, P3i, A3, k3); }
    k_gatherX<<<(k3 * Hdim + 255) / 256, 256>>>(X2, Hdim, P3i, V3, HP, k3);
    // A3 entries can exceed 2048 (not tf32-exact) -> fp32 path; tiny anyway
    h_gcn(A3, k3, HP, Hdim, w3, Hdim, b3, X3, 1, Y, Z, ACC, DINV, CORR);

    // ---- up path ----
    k_copy<<<1024, 256>>>(HA, X2, (size_t)k2 * Hdim);
    k_scatadd<<<(k3 * Hdim + 255) / 256, 256>>>(HA, P3i, X3, k3, Hdim);
    h_gcn(A2, k2, HA, Hdim, uw0, Hdim, ub0, HB, 1, Y, Z, ACC, DINV, CORR);

    k_copy<<<1024, 256>>>(HA, X1, (size_t)k1 * Hdim);
    k_scatadd<<<(k2 * Hdim + 255) / 256, 256>>>(HA, P2i, HB, k2, Hdim);
    h_gcn(A1, k1, HA, Hdim, uw1, Hdim, ub1, HP, 1, Y, Z, ACC, DINV, CORR);

    k_copy<<<1024, 256>>>(HA, X0, (size_t)N * Hdim);
    k_scatadd<<<(k1 * Hdim + 255) / 256, 256>>>(HA, P1i, HP, k1, Hdim);
    h_gcn0(OFFD, LSTD, CNTD, SELF, N, HA, Hdim, uw2, OUT, ub2, HOUTp, 0, Y, Z, ACC, DINV, CORR);

    // ---- layernorm + residual ----
    k_ln<<<N, OUT>>>(HOUTp, ln_g, ln_b, U, OUT);
    h_gemm(RESID, U, res_w, N, OUT, OUT, res_b);

    // ---- GAT layers (sparse attention over mask rows) ----
    k_nbr<<<N, 128>>>(A0, N, NBC, NBL);

    h_gemm(HF, U, g1w, N, HEADS * OUT, OUT, nullptr);
    { dim3 g(N, HEADS); k_attcoef<<<g, OUT>>>(HF, HEADS, OUT, g1as, g1ad, ES, ED); }
    k_gatattn<<<N, 128>>>(HF, ES, ED, NBC, NBL, g1b, nullptr, G1, HEADS, OUT, 1);

    h_gemm(Y, G1, g2w, N, OUT, HEADS * OUT, nullptr);
    { dim3 g(N, 1); k_attcoef<<<g, OUT>>>(Y, 1, OUT, g2as, g2ad, ES, ED); }
    k_gatattn<<<N, 128>>>(Y, ES, ED, NBC, NBL, g2b, RESID, (float*)d_out, 1, OUT, 0);
}

// round 10
// speedup vs baseline: 4.6629x; 2.0243x over previous
#include <cuda_runtime.h>
#include <math.h>
#include <float.h>
#include <stdint.h>

#define MAXN 4096
#define MAXE 65536
#define MAXD 128

// ------------------------- device scratch -------------------------
__device__ float dA1[2048 * 2048];
__device__ float dA2[1024 * 1024];
__device__ float dA3[512 * 512];
__device__ float dMS[2048 * 2048];               // A + I scratch for augment GEMMs

__device__ float dY[(size_t)MAXN * 128];
__device__ float dZ[(size_t)MAXN * 128];
__device__ float dACC[(size_t)MAXN * 128];
__device__ float dSB[4 * 2048 * 64];             // split-K partial buffers

__device__ float dX0[(size_t)MAXN * 64];
__device__ float dX1[2048 * 64];
__device__ float dX2[1024 * 64];
__device__ float dX3[512 * 64];
__device__ float dHP[(size_t)MAXN * 64];
__device__ float dHA[(size_t)MAXN * 64];
__device__ float dHB[(size_t)MAXN * 64];
__device__ float dHOUT[(size_t)MAXN * 128];
__device__ float dU[(size_t)MAXN * 128];
__device__ float dRESID[(size_t)MAXN * 128];
__device__ float dHF[(size_t)MAXN * 512];
__device__ float dG1[(size_t)MAXN * 512];

__device__ float dES[(size_t)MAXN * 4];
__device__ float dED[(size_t)MAXN * 4];
__device__ float dScore[MAXN];
__device__ int   dPerm1[2048];
__device__ int   dPerm2[1024];
__device__ int   dPerm3[512];
__device__ float dVals1[2048];
__device__ float dVals2[1024];
__device__ float dVals3[512];
__device__ float dDinv[MAXN];
__device__ float dCorr[MAXN];

__device__ int dRank[MAXN];
__device__ int dCntS[MAXN], dCntD[MAXN];
__device__ int dSelf[MAXN];
__device__ int dOffS[MAXN + 1], dOffD[MAXN + 1];
__device__ int dFillS[MAXN], dFillD[MAXN];
__device__ int dLstS[MAXE], dLstD[MAXE];
__device__ int dNbrCnt[MAXN];
__device__ int dNbrLst[(size_t)MAXN * MAXD];

// ------------------------- helpers -------------------------
__device__ __forceinline__ float lrelu(float x) { return x > 0.f ? x : 0.2f * x; }

// zero A1/A2/A3 (mma targets), rank=-1, counts=0
__global__ void k_zero_misc(float* A1, float* A2, float* A3, int* rank,
                            int* c0, int* c1, int* c2, int* c3, int* c4, int n) {
    size_t i = (size_t)blockIdx.x * blockDim.x + threadIdx.x;
    size_t stride = (size_t)gridDim.x * blockDim.x;
    for (size_t j = i; j < (size_t)2048 * 2048; j += stride) A1[j] = 0.f;
    for (size_t j = i; j < (size_t)1024 * 1024; j += stride) A2[j] = 0.f;
    for (size_t j = i; j < (size_t)512 * 512; j += stride) A3[j] = 0.f;
    for (size_t j = i; j < (size_t)n; j += stride) {
        rank[j] = -1; c0[j] = 0; c1[j] = 0; c2[j] = 0; c3[j] = 0; c4[j] = 0;
    }
}

__global__ void k_build_cnt(const int* ei, int E, int* cntS, int* cntD, int* selfc) {
    int e = blockIdx.x * blockDim.x + threadIdx.x;
    if (e >= E) return;
    int s = ei[e], d = ei[E + e];
    atomicAdd(&cntS[s], 1);
    atomicAdd(&cntD[d], 1);
    if (s == d) atomicAdd(&selfc[d], 1);
}

__global__ void k_scan2(const int* cntS, int* offS, const int* cntD, int* offD, int n) {
    __shared__ int ps[1024];
    const int* cnt = blockIdx.x == 0 ? cntS : cntD;
    int* off = blockIdx.x == 0 ? offS : offD;
    int t = threadIdx.x;
    int chunk = (n + 1023) >> 10;
    int base = t * chunk;
    int s = 0;
    for (int j = 0; j < chunk; j++) { int idx = base + j; if (idx < n) s += cnt[idx]; }
    ps[t] = s; __syncthreads();
    for (int d = 1; d < 1024; d <<= 1) {
        int v = (t >= d) ? ps[t - d] : 0;
        __syncthreads();
        ps[t] += v;
        __syncthreads();
    }
    int run = (t > 0) ? ps[t - 1] : 0;
    if (t == 0) off[0] = 0;
    for (int j = 0; j < chunk; j++) {
        int idx = base + j;
        if (idx < n) { run += cnt[idx]; off[idx + 1] = run; }
    }
}

__global__ void k_csr_fill(const int* ei, int E, const int* offS, const int* offD,
                           int* fillS, int* fillD, int* lstS, int* lstD) {
    int e = blockIdx.x * blockDim.x + threadIdx.x;
    if (e >= E) return;
    int s = ei[e], d = ei[E + e];
    int pS = atomicAdd(&fillS[s], 1);
    lstS[offS[s] + pS] = d;
    int pD = atomicAdd(&fillD[d], 1);
    lstD[offD[d] + pD] = s;
}

__global__ void k_fill_rank(const int* perm, int k, int* rank) {
    int i = blockIdx.x * blockDim.x + threadIdx.x;
    if (i < k) rank[perm[i]] = i;
}

// A1[ri][rj] += 1 for each 2-path j->k->i with both ends in perm1 (i != j)
__global__ void k_spgemm_ranked(const int* cntS, const int* cntD, const int* offS, const int* offD,
                                const int* lstS, const int* lstD, const int* rank,
                                float* A1, int k1) {
    int k = blockIdx.x;
    int ni = cntS[k], nj = cntD[k];
    long tot = (long)ni * nj;
    int oS = offS[k], oD = offD[k];
    for (long p = threadIdx.x; p < tot; p += blockDim.x) {
        int i = lstS[oS + (int)(p / nj)];
        int j = lstD[oD + (int)(p % nj)];
        int ri = rank[i], rj = rank[j];
        if (ri >= 0 && rj >= 0 && ri != rj)
            atomicAdd(&A1[(size_t)ri * k1 + rj], 1.f);
    }
}

// A1[rd][rs] += 2 for each edge s->d with both ends in perm1 (d != s)
__global__ void k_add2a_ranked(const int* ei, int E, const int* rank, float* A1, int k1) {
    int e = blockIdx.x * blockDim.x + threadIdx.x;
    if (e >= E) return;
    int s = ei[e], d = ei[E + e];
    int rs = rank[s], rd = rank[d];
    if (rs >= 0 && rd >= 0 && rs != rd)
        atomicAdd(&A1[(size_t)rd * k1 + rs], 2.f);
}

__global__ void k_zero_diag(float* C, int n) {
    int i = blockIdx.x * blockDim.x + threadIdx.x;
    if (i < n) C[(size_t)i * n + i] = 0.f;
}

__global__ void k_copy_addI(const float* A, float* M, int n) {
    size_t idx = (size_t)blockIdx.x * blockDim.x + threadIdx.x;
    size_t tot = (size_t)n * n;
    size_t stride = (size_t)gridDim.x * blockDim.x;
    for (; idx < tot; idx += stride) {
        int i = (int)(idx / n), j = (int)(idx % n);
        M[idx] = A[idx] + (i == j ? 1.f : 0.f);
    }
}

// ------------------------- SGEMM (+ optional split-K via gridDim.z) -------------------------
// gridDim.z>1: writes partial for K-chunk z into C + z*M*N (no bias); else full GEMM.
__global__ void k_gemm(const float* __restrict__ A, const float* __restrict__ B,
                       float* __restrict__ Cbase, int M, int N, int K,
                       const float* __restrict__ bias) {
    __shared__ float As[16][64];
    __shared__ float Bs[16][64];
    int tid = threadIdx.x;
    int tx = tid & 15, ty = tid >> 4;
    int bm = blockIdx.y * 64, bn = blockIdx.x * 64;
    int zs = gridDim.z;
    int Kc = K / zs;
    int kbeg = blockIdx.z * Kc;
    int kend = (blockIdx.z == zs - 1) ? K : kbeg + Kc;
    float* C = (zs > 1) ? Cbase + (size_t)blockIdx.z * M * N : Cbase;
    float acc[4][4] = {};
    for (int k0 = kbeg; k0 < kend; k0 += 16) {
#pragma unroll
        for (int l = 0; l < 4; l++) {
            int e = tid + l * 256;
            int mm = e >> 4, kk = e & 15;
            int gr = bm + mm, gc = k0 + kk;
            As[kk][mm] = (gr < M && gc < kend) ? A[(size_t)gr * K + gc] : 0.f;
        }
#pragma unroll
        for (int l = 0; l < 4; l++) {
            int e = tid + l * 256;
            int kk = e >> 6, nn = e & 63;
            int gr = k0 + kk, gc = bn + nn;
            Bs[kk][nn] = (gr < kend && gc < N) ? B[(size_t)gr * N + gc] : 0.f;
        }
        __syncthreads();
#pragma unroll
        for (int kk = 0; kk < 16; kk++) {
            float a[4], b[4];
#pragma unroll
            for (int i = 0; i < 4; i++) a[i] = As[kk][ty * 4 + i];
#pragma unroll
            for (int j = 0; j < 4; j++) b[j] = Bs[kk][tx * 4 + j];
#pragma unroll
            for (int i = 0; i < 4; i++)
#pragma unroll
                for (int j = 0; j < 4; j++) acc[i][j] += a[i] * b[j];
        }
        __syncthreads();
    }
#pragma unroll
    for (int i = 0; i < 4; i++) {
        int r = bm + ty * 4 + i;
        if (r >= M) continue;
#pragma unroll
        for (int j = 0; j < 4; j++) {
            int c = bn + tx * 4 + j;
            if (c >= N) continue;
            float v = acc[i][j];
            if (bias) v += bias[c];
            C[(size_t)r * N + c] = v;
        }
    }
}

// fixed-order reduction of 4 split-K partials (deterministic)
__global__ void k_red4(float* out, const float* S, size_t nf) {
    size_t i = (size_t)blockIdx.x * blockDim.x + threadIdx.x;
    if (i >= nf) return;
    out[i] = ((S[i] + S[nf + i]) + S[2 * nf + i]) + S[3 * nf + i];
}

// ------------------------- gathered TF32 tensor-core GEMM -------------------------
// C[M,N] (ldc=N) += A[permA[m], :] @ B[:, permB[n]] for K-chunk z (atomicAdd; C pre-zeroed).
// All inputs are small integers -> tf32-exact; partials are integers -> atomicAdd bit-exact.
__device__ __forceinline__ void mma_tf32_op(float* c, const uint32_t* a, const uint32_t* b) {
    asm volatile(
        "mma.sync.aligned.m16n8k8.row.col.f32.tf32.tf32.f32 "
        "{%0,%1,%2,%3}, {%4,%5,%6,%7}, {%8,%9}, {%0,%1,%2,%3};"
        : "+f"(c[0]), "+f"(c[1]), "+f"(c[2]), "+f"(c[3])
        : "r"(a[0]), "r"(a[1]), "r"(a[2]), "r"(a[3]), "r"(b[0]), "r"(b[1]));
}

__global__ void __launch_bounds__(256)
k_mma_gather(const float* __restrict__ A, int lda, const float* __restrict__ B, int ldb,
             float* __restrict__ C, int M, int N, int K,
             const int* __restrict__ permA, const int* __restrict__ permB) {
    __shared__ float As[128][36];
    __shared__ float Bs[128][36];
    __shared__ int sPA[128], sPB[128];
    int tid = threadIdx.x;
    int lane = tid & 31, warp = tid >> 5;
    int wm = warp >> 2, wn = warp & 3;
    int g = lane >> 2, tg = lane & 3;
    int bm = blockIdx.y * 128, bn = blockIdx.x * 128;
    int zs = gridDim.z;
    int Kc = K / zs;
    int kbeg = blockIdx.z * Kc, kend = kbeg + Kc;

    if (tid < 128) {
        sPA[tid] = (bm + tid < M) ? permA[bm + tid] : 0;
        sPB[tid] = (bn + tid < N) ? permB[bn + tid] : 0;
    }
    __syncthreads();

    float acc[4][4][4] = {};
    for (int k0 = kbeg; k0 < kend; k0 += 32) {
        // A tile: gathered rows, coalesced float4 along K
#pragma unroll
        for (int i = 0; i < 4; i++) {
            int flat = tid + i * 256;
            int r = flat >> 3, c4 = (flat & 7) * 4;
            float4 v = make_float4(0.f, 0.f, 0.f, 0.f);
            if (bm + r < M) v = *(const float4*)&A[(size_t)sPA[r] * lda + k0 + c4];
            *(float4*)&As[r][c4] = v;
        }
        // B tile: gathered columns (scalar loads), transposed into [n][k]
#pragma unroll
        for (int i = 0; i < 4; i++) {
            int flat = tid + i * 256;
            int kr = flat >> 5, c4 = (flat & 31) * 4;
            const float* bp = &B[(size_t)(k0 + kr) * ldb];
#pragma unroll
            for (int u = 0; u < 4; u++) {
                int c = c4 + u;
                Bs[c][kr] = (bn + c < N) ? bp[sPB[c]] : 0.f;
            }
        }
        __syncthreads();
#pragma unroll
        for (int ks = 0; ks < 32; ks += 8) {
            uint32_t af[4][4], bf[4][2];
#pragma unroll
            for (int mt = 0; mt < 4; mt++) {
                int m = wm * 64 + mt * 16;
                af[mt][0] = __float_as_uint(As[m + g][ks + tg]);
                af[mt][1] = __float_as_uint(As[m + g + 8][ks + tg]);
                af[mt][2] = __float_as_uint(As[m + g][ks + tg + 4]);
                af[mt][3] = __float_as_uint(As[m + g + 8][ks + tg + 4]);
            }
#pragma unroll
            for (int nt = 0; nt < 4; nt++) {
                int n = wn * 32 + nt * 8;
                bf[nt][0] = __float_as_uint(Bs[n + g][ks + tg]);
                bf[nt][1] = __float_as_uint(Bs[n + g][ks + tg + 4]);
            }
#pragma unroll
            for (int mt = 0; mt < 4; mt++)
#pragma unroll
                for (int nt = 0; nt < 4; nt++)
                    mma_tf32_op(acc[mt][nt], af[mt], bf[nt]);
        }
        __syncthreads();
    }
#pragma unroll
    for (int mt = 0; mt < 4; mt++) {
#pragma unroll
        for (int nt = 0; nt < 4; nt++) {
            int row0 = bm + wm * 64 + mt * 16 + g;
            int col = bn + wn * 32 + nt * 8 + tg * 2;
            float* c = acc[mt][nt];
            if (row0 < M) {
                float* p = &C[(size_t)row0 * N];
                if (col < N)     atomicAdd(&p[col], c[0]);
                if (col + 1 < N) atomicAdd(&p[col + 1], c[1]);
            }
            int row1 = row0 + 8;
            if (row1 < M) {
                float* p = &C[(size_t)row1 * N];
                if (col < N)     atomicAdd(&p[col], c[2]);
                if (col + 1 < N) atomicAdd(&p[col + 1], c[3]);
            }
        }
    }
}

// ------------------------- GCN pieces -------------------------
__global__ void k_rowstats(const float* A, int n, float* dinv, float* corr) {
    int r = blockIdx.x, t = threadIdx.x;
    __shared__ float sh[256];
    float s = 0.f;
    for (int j = t; j < n; j += 256) s += A[(size_t)r * n + j];
    sh[t] = s; __syncthreads();
    for (int st = 128; st > 0; st >>= 1) { if (t < st) sh[t] += sh[t + st]; __syncthreads(); }
    if (t == 0) {
        float diag = A[(size_t)r * n + r];
        float ex = (diag == 0.f) ? 2.f : 0.f;
        dinv[r] = 1.f / sqrtf(sh[0] + ex);
        corr[r] = ex;
    }
}

__global__ void k_rowstats_csr(const int* cntD, const int* selfc, float* dinv, float* corr, int n) {
    int d = blockIdx.x * blockDim.x + threadIdx.x;
    if (d >= n) return;
    float ex = (selfc[d] == 0) ? 2.f : 0.f;
    dinv[d] = 1.f / sqrtf((float)cntD[d] + ex);
    corr[d] = ex;
}

__global__ void k_scale_rows(const float* Y, const float* dinv, float* Z, int n, int F) {
    size_t idx = (size_t)blockIdx.x * blockDim.x + threadIdx.x;
    if (idx >= (size_t)n * F) return;
    Z[idx] = dinv[idx / F] * Y[idx];
}

__global__ void k_spmm(const int* __restrict__ offD, const int* __restrict__ lstD,
                       const float* __restrict__ Z, float* __restrict__ ACC, int F) {
    int d = blockIdx.x, f = threadIdx.x;
    int b = offD[d], e = offD[d + 1];
    float acc = 0.f;
    for (int i = b; i < e; i++) acc += Z[(size_t)lstD[i] * F + f];
    ACC[(size_t)d * F + f] = acc;
}

__global__ void k_gcn_epi(const float* ACC, const float* Z, const float* dinv, const float* corr,
                          const float* b, float* out, int n, int F, int relu) {
    size_t idx = (size_t)blockIdx.x * blockDim.x + threadIdx.x;
    if (idx >= (size_t)n * F) return;
    int i = (int)(idx / F), f = (int)(idx % F);
    float v = dinv[i] * (ACC[idx] + corr[i] * Z[idx]) + b[f];
    if (relu) v = fmaxf(v, 0.f);
    out[idx] = v;
}

// ------------------------- pooling -------------------------
__global__ void k_score(const float* x, const float* p, float* score) {
    int i = blockIdx.x, t = threadIdx.x;
    __shared__ float s1[64], s2[64];
    float xv = x[(size_t)i * 64 + t], pv = p[t];
    s1[t] = xv * pv; s2[t] = pv * pv; __syncthreads();
    for (int st = 32; st > 0; st >>= 1) {
        if (t < st) { s1[t] += s1[t + st]; s2[t] += s2[t + st]; }
        __syncthreads();
    }
    if (t == 0) score[i] = tanhf(s1[0] / sqrtf(s2[0]));
}

__global__ void k_topsort(const float* score, int n, int k, int N2, int* perm, float* vals) {
    __shared__ float sv[4096];
    __shared__ int si[4096];
    int t = threadIdx.x;
    for (int i = t; i < N2; i += blockDim.x) {
        if (i < n) { sv[i] = score[i]; si[i] = i; }
        else       { sv[i] = -FLT_MAX; si[i] = 0x3fffffff; }
    }
    __syncthreads();
    for (int size = 2; size <= N2; size <<= 1) {
        for (int stride = size >> 1; stride > 0; stride >>= 1) {
            for (int i = t; i < N2; i += blockDim.x) {
                int j = i ^ stride;
                if (j > i) {
                    float av = sv[i]; int ai = si[i];
                    float bv = sv[j]; int bi = si[j];
                    bool before = (av > bv) || (av == bv && ai < bi);
                    bool desc = ((i & size) == 0);
                    if (desc != before) { sv[i] = bv; si[i] = bi; sv[j] = av; si[j] = ai; }
                }
            }
            __syncthreads();
        }
    }
    for (int i = t; i < k; i += blockDim.x) { perm[i] = si[i]; vals[i] = sv[i]; }
}

__global__ void k_gatherX(const float* X, int F, const int* perm, const float* vals, float* out, int k) {
    size_t idx = (size_t)blockIdx.x * blockDim.x + threadIdx.x;
    if (idx >= (size_t)k * F) return;
    int i = (int)(idx / F), f = (int)(idx % F);
    out[idx] = X[(size_t)perm[i] * F + f] * vals[i];
}

__global__ void k_copy(float* dst, const float* src, size_t n) {
    size_t i = (size_t)blockIdx.x * blockDim.x + threadIdx.x;
    size_t stride = (size_t)gridDim.x * blockDim.x;
    for (; i < n; i += stride) dst[i] = src[i];
}

__global__ void k_scatadd(float* h, const int* perm, const float* xl, int k, int F) {
    size_t idx = (size_t)blockIdx.x * blockDim.x + threadIdx.x;
    if (idx >= (size_t)k * F) return;
    int t = (int)(idx / F), f = (int)(idx % F);
    h[(size_t)perm[t] * F + f] += xl[idx];
}

// ------------------------- layernorm -------------------------
__global__ void k_ln(const float* h, const float* g, const float* b, float* u, int F) {
    int row = blockIdx.x, t = threadIdx.x;
    __shared__ float sh[128];
    float v = h[(size_t)row * F + t];
    sh[t] = v; __syncthreads();
    for (int st = 64; st > 0; st >>= 1) { if (t < st) sh[t] += sh[t + st]; __syncthreads(); }
    float mu = sh[0] / F;
    __syncthreads();
    float dv = v - mu;
    sh[t] = dv * dv; __syncthreads();
    for (int st = 64; st > 0; st >>= 1) { if (t < st) sh[t] += sh[t + st]; __syncthreads(); }
    float var = sh[0] / F;
    u[(size_t)row * F + t] = dv * rsqrtf(var + 1e-6f) * g[t] + b[t];
}

// ------------------------- GAT -------------------------
// distinct in-neighbors (union self) straight from CSR, per-dst dedupe
__global__ void k_nbr_csr(const int* offD, const int* lstD, int* cnt, int* lst) {
    int d = blockIdx.x, t = threadIdx.x;  // block 128
    __shared__ int sl[MAXD];
    __shared__ unsigned char kf[MAXD];
    int b = offD[d], e = offD[d + 1];
    int m = e - b; if (m > MAXD) m = MAXD;
    if (t < m) sl[t] = lstD[b + t];
    __syncthreads();
    if (t < m) {
        int v = sl[t]; bool keep = true;
        for (int j = 0; j < t; j++) if (sl[j] == v) { keep = false; break; }
        kf[t] = keep ? 1 : 0;
    }
    __syncthreads();
    if (t == 0) {
        int c = 0; bool self = false;
        for (int i = 0; i < m; i++) {
            if (kf[i]) {
                lst[(size_t)d * MAXD + c++] = sl[i];
                if (sl[i] == d) self = true;
            }
        }
        if (!self && c < MAXD) lst[(size_t)d * MAXD + c++] = d;
        cnt[d] = c;
    }
}

__global__ void k_attcoef(const float* hf, int H, int C, const float* asrc, const float* adst,
                          float* es, float* ed) {
    int s = blockIdx.x, h = blockIdx.y, t = threadIdx.x;
    __shared__ float s1[128], s2[128];
    float x = hf[(size_t)s * H * C + h * C + t];
    s1[t] = x * asrc[h * C + t];
    s2[t] = x * adst[h * C + t];
    __syncthreads();
    for (int st = 64; st > 0; st >>= 1) {
        if (t < st) { s1[t] += s1[t + st]; s2[t] += s2[t + st]; }
        __syncthreads();
    }
    if (t == 0) { es[s * H + h] = s1[0]; ed[s * H + h] = s2[0]; }
}

__global__ void k_gatattn(const float* hf, const float* es, const float* ed,
                          const int* cnt, const int* lst, const float* bias,
                          const float* resid, float* out, int H, int C, int doElu) {
    int d = blockIdx.x, t = threadIdx.x;
    __shared__ int snb[MAXD];
    __shared__ float sw[MAXD];
    __shared__ float sred[128];
    int m = cnt[d];
    if (t < m) snb[t] = lst[(size_t)d * MAXD + t];
    __syncthreads();
    for (int h = 0; h < H; h++) {
        float edv = ed[d * H + h];
        float mx = -FLT_MAX;
        for (int i = t; i < m; i += 128) mx = fmaxf(mx, lrelu(edv + es[snb[i] * H + h]));
        sred[t] = mx; __syncthreads();
        for (int st = 64; st > 0; st >>= 1) { if (t < st) sred[t] = fmaxf(sred[t], sred[t + st]); __syncthreads(); }
        float M = sred[0];
        __syncthreads();
        float dp = 0.f;
        for (int i = t; i < m; i += 128) {
            float w = expf(lrelu(edv + es[snb[i] * H + h]) - M);
            sw[i] = w; dp += w;
        }
        sred[t] = dp; __syncthreads();
        for (int st = 64; st > 0; st >>= 1) { if (t < st) sred[t] += sred[t + st]; __syncthreads(); }
        float den = sred[0];
        __syncthreads();
        float num = 0.f;
        for (int i = 0; i < m; i++) num += sw[i] * hf[(size_t)snb[i] * H * C + h * C + t];
        float o = num / den + bias[h * C + t];
        if (doElu) o = o > 0.f ? o : (expf(o) - 1.f);
        if (resid) o += resid[(size_t)d * C + t];
        out[(size_t)d * H * C + h * C + t] = o;
        __syncthreads();
    }
}

// ------------------------- host orchestration -------------------------
static void h_gemm(float* C, const float* A, const float* B, int M, int N, int K, const float* bias) {
    dim3 g((N + 63) / 64, (M + 63) / 64);
    k_gemm<<<g, 256>>>(A, B, C, M, N, K, bias);
}

// dense GCN (levels 1..3): split-K fp32 propagation (deterministic partial buffers)
static void h_gcn(const float* A, int n, const float* x, int Fin, const float* W, int Fout,
                  const float* bias, float* out, int relu,
                  float* Y, float* Z, float* ACC, float* SBUF, float* dinv, float* corr) {
    h_gemm(Y, x, W, n, Fout, Fin, nullptr);
    k_rowstats<<<n, 256>>>(A, n, dinv, corr);
    int tot = n * Fout;
    k_scale_rows<<<(tot + 255) / 256, 256>>>(Y, dinv, Z, n, Fout);
    dim3 g((Fout + 63) / 64, (n + 63) / 64, 4);      // split-K x4
    k_gemm<<<g, 256>>>(A, Z, SBUF, n, Fout, n, nullptr);
    k_red4<<<(tot + 255) / 256, 256>>>(ACC, SBUF, (size_t)tot);
    k_gcn_epi<<<(tot + 255) / 256, 256>>>(ACC, Z, dinv, corr, bias, out, n, Fout, relu);
}

// sparse GCN for level 0 (A0 CSR)
static void h_gcn0(const int* offD, const int* lstD, const int* cntD, const int* selfc,
                   int n, const float* x, int Fin, const float* W, int Fout,
                   const float* bias, float* out, int relu,
                   float* Y, float* Z, float* ACC, float* dinv, float* corr) {
    h_gemm(Y, x, W, n, Fout, Fin, nullptr);
    k_rowstats_csr<<<(n + 255) / 256, 256>>>(cntD, selfc, dinv, corr, n);
    int tot = n * Fout;
    k_scale_rows<<<(tot + 255) / 256, 256>>>(Y, dinv, Z, n, Fout);
    k_spmm<<<n, Fout>>>(offD, lstD, Z, ACC, Fout);
    k_gcn_epi<<<(tot + 255) / 256, 256>>>(ACC, Z, dinv, corr, bias, out, n, Fout, relu);
}

extern "C" void kernel_launch(void* const* d_in, const int* in_sizes, int n_in,
                              void* d_out, int out_size) {
    const float* x        = (const float*)d_in[0];
    const int*   ei       = (const int*)d_in[1];
    const float* w0 = (const float*)d_in[2];  const float* b0 = (const float*)d_in[3];
    const float* w1 = (const float*)d_in[4];  const float* b1 = (const float*)d_in[5];
    const float* w2 = (const float*)d_in[6];  const float* b2 = (const float*)d_in[7];
    const float* w3 = (const float*)d_in[8];  const float* b3 = (const float*)d_in[9];
    const float* p1 = (const float*)d_in[10]; const float* p2 = (const float*)d_in[11];
    const float* p3 = (const float*)d_in[12];
    const float* uw0 = (const float*)d_in[13]; const float* ub0 = (const float*)d_in[14];
    const float* uw1 = (const float*)d_in[15]; const float* ub1 = (const float*)d_in[16];
    const float* uw2 = (const float*)d_in[17]; const float* ub2 = (const float*)d_in[18];
    const float* ln_g = (const float*)d_in[19]; const float* ln_b = (const float*)d_in[20];
    const float* res_w = (const float*)d_in[21]; const float* res_b = (const float*)d_in[22];
    const float* g1w = (const float*)d_in[23];
    const float* g1as = (const float*)d_in[24]; const float* g1ad = (const float*)d_in[25];
    const float* g1b = (const float*)d_in[26];
    const float* g2w = (const float*)d_in[27];
    const float* g2as = (const float*)d_in[28]; const float* g2ad = (const float*)d_in[29];
    const float* g2b = (const float*)d_in[30];

    int Hdim  = in_sizes[3];                 // 64
    int INF   = in_sizes[2] / Hdim;          // 3
    int N     = in_sizes[0] / INF;           // 4096
    int E     = in_sizes[1] / 2;             // 65536
    int OUT   = in_sizes[18];                // 128
    int HEADS = in_sizes[26] / OUT;          // 4

    float *A1, *A2, *A3, *MS;
    float *Y, *Z, *ACC, *SBUF, *X0, *X1, *X2, *X3, *HP, *HA, *HB, *HOUTp, *U, *RESID, *HF, *G1;
    float *ES, *ED, *SCORE, *V1, *V2, *V3, *DINV, *CORR;
    int *RANK, *P1i, *P2i, *P3i, *CNTS, *CNTD, *SELF, *OFFS, *OFFD, *FILLS, *FILLD, *LSTS, *LSTD, *NBC, *NBL;
    cudaGetSymbolAddress((void**)&A1, dA1);   cudaGetSymbolAddress((void**)&A2, dA2);
    cudaGetSymbolAddress((void**)&A3, dA3);   cudaGetSymbolAddress((void**)&MS, dMS);
    cudaGetSymbolAddress((void**)&Y, dY);     cudaGetSymbolAddress((void**)&Z, dZ);
    cudaGetSymbolAddress((void**)&ACC, dACC); cudaGetSymbolAddress((void**)&SBUF, dSB);
    cudaGetSymbolAddress((void**)&X0, dX0);
    cudaGetSymbolAddress((void**)&X1, dX1);   cudaGetSymbolAddress((void**)&X2, dX2);
    cudaGetSymbolAddress((void**)&X3, dX3);   cudaGetSymbolAddress((void**)&HP, dHP);
    cudaGetSymbolAddress((void**)&HA, dHA);   cudaGetSymbolAddress((void**)&HB, dHB);
    cudaGetSymbolAddress((void**)&HOUTp, dHOUT); cudaGetSymbolAddress((void**)&U, dU);
    cudaGetSymbolAddress((void**)&RESID, dRESID); cudaGetSymbolAddress((void**)&HF, dHF);
    cudaGetSymbolAddress((void**)&G1, dG1);
    cudaGetSymbolAddress((void**)&ES, dES);   cudaGetSymbolAddress((void**)&ED, dED);
    cudaGetSymbolAddress((void**)&SCORE, dScore);
    cudaGetSymbolAddress((void**)&P1i, dPerm1); cudaGetSymbolAddress((void**)&P2i, dPerm2);
    cudaGetSymbolAddress((void**)&P3i, dPerm3);
    cudaGetSymbolAddress((void**)&V1, dVals1); cudaGetSymbolAddress((void**)&V2, dVals2);
    cudaGetSymbolAddress((void**)&V3, dVals3);
    cudaGetSymbolAddress((void**)&DINV, dDinv); cudaGetSymbolAddress((void**)&CORR, dCorr);
    cudaGetSymbolAddress((void**)&RANK, dRank);
    cudaGetSymbolAddress((void**)&CNTS, dCntS); cudaGetSymbolAddress((void**)&CNTD, dCntD);
    cudaGetSymbolAddress((void**)&SELF, dSelf);
    cudaGetSymbolAddress((void**)&OFFS, dOffS); cudaGetSymbolAddress((void**)&OFFD, dOffD);
    cudaGetSymbolAddress((void**)&FILLS, dFillS); cudaGetSymbolAddress((void**)&FILLD, dFillD);
    cudaGetSymbolAddress((void**)&LSTS, dLstS); cudaGetSymbolAddress((void**)&LSTD, dLstD);
    cudaGetSymbolAddress((void**)&NBC, dNbrCnt); cudaGetSymbolAddress((void**)&NBL, dNbrLst);

    int k1 = (N + 1) / 2, k2 = (k1 + 1) / 2, k3 = (k2 + 1) / 2;

    // ---- init + CSR build (no dense A0, no dense B0) ----
    k_zero_misc<<<2048, 256>>>(A1, A2, A3, RANK, CNTS, CNTD, FILLS, FILLD, SELF, N);
    k_build_cnt<<<(E + 255) / 256, 256>>>(ei, E, CNTS, CNTD, SELF);
    k_scan2<<<2, 1024>>>(CNTS, OFFS, CNTD, OFFD, N);
    k_csr_fill<<<(E + 255) / 256, 256>>>(ei, E, OFFS, OFFD, FILLS, FILLD, LSTS, LSTD);

    // ---- level 0 GCN (sparse) ----
    h_gcn0(OFFD, LSTD, CNTD, SELF, N, x, INF, w0, Hdim, b0, X0, 1, Y, Z, ACC, DINV, CORR);

    // ---- pool1: perm from scores, then build A1 = augment(A0)[perm1,perm1] sparsely ----
    k_score<<<N, 64>>>(X0, p1, SCORE);
    k_topsort<<<1, 1024>>>(SCORE, N, k1, 4096, P1i, V1);
    k_fill_rank<<<(k1 + 255) / 256, 256>>>(P1i, k1, RANK);
    k_add2a_ranked<<<(E + 255) / 256, 256>>>(ei, E, RANK, A1, k1);
    k_spgemm_ranked<<<N, 256>>>(CNTS, CNTD, OFFS, OFFD, LSTS, LSTD, RANK, A1, k1);
    k_gatherX<<<(k1 * Hdim + 255) / 256, 256>>>(X0, Hdim, P1i, V1, HP, k1);
    h_gcn(A1, k1, HP, Hdim, w1, Hdim, b1, X1, 1, Y, Z, ACC, SBUF, DINV, CORR);

    // ---- pool2: A2 = (MS@MS)[perm2,perm2] via gathered tf32 mma (4.3 GF vs 17.2) ----
    k_copy_addI<<<2048, 256>>>(A1, MS, k1);
    k_score<<<k1, 64>>>(X1, p2, SCORE);
    k_topsort<<<1, 1024>>>(SCORE, k1, k2, 2048, P2i, V2);
    { dim3 g(k2 / 128, k2 / 128, 4);
      k_mma_gather<<<g, 256>>>(MS, k1, MS, k1, A2, k2, k2, k1, P2i, P2i); }
    k_zero_diag<<<(k2 + 255) / 256, 256>>>(A2, k2);
    k_gatherX<<<(k2 * Hdim + 255) / 256, 256>>>(X1, Hdim, P2i, V2, HP, k2);
    h_gcn(A2, k2, HP, Hdim, w2, Hdim, b2, X2, 1, Y, Z, ACC, SBUF, DINV, CORR);

    // ---- pool3: A3 = (MS2@MS2)[perm3,perm3] via gathered tf32 mma ----
    k_copy_addI<<<2048, 256>>>(A2, MS, k2);
    k_score<<<k2, 64>>>(X2, p3, SCORE);
    k_topsort<<<1, 1024>>>(SCORE, k2, k3, 1024, P3i, V3);
    { dim3 g(k3 / 128, k3 / 128, 8);
      k_mma_gather<<<g, 256>>>(MS, k2, MS, k2, A3, k3, k3, k2, P3i, P3i); }
    k_zero_diag<<<(k3 + 255) / 256, 256>>>(A3, k3);
    k_gatherX<<<(k3 * Hdim + 255) / 256, 256>>>(X2, Hdim, P3i, V3, HP, k3);
    h_gcn(A3, k3, HP, Hdim, w3, Hdim, b3, X3, 1, Y, Z, ACC, SBUF, DINV, CORR);

    // ---- up path ----
    k_copy<<<1024, 256>>>(HA, X2, (size_t)k2 * Hdim);
    k_scatadd<<<(k3 * Hdim + 255) / 256, 256>>>(HA, P3i, X3, k3, Hdim);
    h_gcn(A2, k2, HA, Hdim, uw0, Hdim, ub0, HB, 1, Y, Z, ACC, SBUF, DINV, CORR);

    k_copy<<<1024, 256>>>(HA, X1, (size_t)k1 * Hdim);
    k_scatadd<<<(k2 * Hdim + 255) / 256, 256>>>(HA, P2i, HB, k2, Hdim);
    h_gcn(A1, k1, HA, Hdim, uw1, Hdim, ub1, HP, 1, Y, Z, ACC, SBUF, DINV, CORR);

    k_copy<<<1024, 256>>>(HA, X0, (size_t)N * Hdim);
    k_scatadd<<<(k1 * Hdim + 255) / 256, 256>>>(HA, P1i, HP, k1, Hdim);
    h_gcn0(OFFD, LSTD, CNTD, SELF, N, HA, Hdim, uw2, OUT, ub2, HOUTp, 0, Y, Z, ACC, DINV, CORR);

    // ---- layernorm + residual ----
    k_ln<<<N, OUT>>>(HOUTp, ln_g, ln_b, U, OUT);
    h_gemm(RESID, U, res_w, N, OUT, OUT, res_b);

    // ---- GAT layers (sparse attention from CSR neighbor lists) ----
    k_nbr_csr<<<N, 128>>>(OFFD, LSTD, NBC, NBL);

    h_gemm(HF, U, g1w, N, HEADS * OUT, OUT, nullptr);
    { dim3 g(N, HEADS); k_attcoef<<<g, OUT>>>(HF, HEADS, OUT, g1as, g1ad, ES, ED); }
    k_gatattn<<<N, 128>>>(HF, ES, ED, NBC, NBL, g1b, nullptr, G1, HEADS, OUT, 1);

    h_gemm(Y, G1, g2w, N, OUT, HEADS * OUT, nullptr);
    { dim3 g(N, 1); k_attcoef<<<g, OUT>>>(Y, 1, OUT, g2as, g2ad, ES, ED); }
    k_gatattn<<<N, 128>>>(Y, ES, ED, NBC, NBL, g2b, RESID, (float*)d_out, 1, OUT, 0);
}